// round 11
// baseline (speedup 1.0000x reference)
#include <cuda_runtime.h>
#include <cuda_fp16.h>
#include <cstdint>

#define WW 48
#define HH 48
#define NQ 2304
#define NHD 8
#define EE 64
#define BB 8
#define CC 512
#define TW 95
#define TT (TW*TW)
#define LOG2E 1.4426950408889634f

#define QT 128            // M per block
#define NCOL 256          // N per block
#define NW32 (CC*NQ/2)    // b32 words in X operand (589824)
#define NWW (EE*CC)       // wsplit items (32768)
#define XWB (NW32/256)    // 2304 x-pack blocks
#define WWB ((NWW+255)/256) // 128 w-split blocks
#define SKIP_THRESH (-18.0f)

// ---- device scratch ----
__device__ float g_S[NHD * TT];
__device__ float g_cm[NHD * TW * HH];
__device__ float g_M[NHD * NQ];
__device__ __align__(256) uint4 g_Xbh4[NW32 / 4];   // X fp16, fragment-major [g][kx][ks][lane][word]
__device__ __align__(16) __half g_Upk[NQ * BB * NHD * EE];  // U fp16: [q][b][n*64+e]
__device__ __align__(16) __half g_Wth[EE * CC];     // W^T hi fp16: [eo][f=n*64+e]
__device__ __align__(16) __half g_Wtl[EE * CC];     // W^T lo

__device__ __forceinline__ float fexp2(float x) {
    float y; asm("ex2.approx.ftz.f32 %0, %1;" : "=f"(y) : "f"(x)); return y;
}
__device__ __forceinline__ uint32_t smem_u32(const void* p) {
    uint32_t a;
    asm("{ .reg .u64 t; cvta.to.shared.u64 t, %1; cvt.u32.u64 %0, t; }" : "=r"(a) : "l"(p));
    return a;
}
__device__ __forceinline__ void cpa16(uint32_t dst, const void* src) {
    asm volatile("cp.async.cg.shared.global [%0], [%1], 16;" :: "r"(dst), "l"(src));
}
__device__ __forceinline__ void mma16816h(float* c, const uint4& a, const uint2& b) {
    asm volatile(
        "mma.sync.aligned.m16n8k16.row.col.f32.f16.f16.f32 "
        "{%0,%1,%2,%3}, {%4,%5,%6,%7}, {%8,%9}, {%0,%1,%2,%3};"
        : "+f"(c[0]), "+f"(c[1]), "+f"(c[2]), "+f"(c[3])
        : "r"(a.x), "r"(a.y), "r"(a.z), "r"(a.w), "r"(b.x), "r"(b.y));
}

// ---------------------------------------------------------------------------
// ONE fused prep kernel.
// blocks [0,8):        per-head table -> colmax -> rowmax (phased via syncthreads)
// blocks [8, 8+WWB):   W^T split hi/lo
// blocks [8+WWB, ...): X fragment-pack fp16
__global__ void k_prep(const float* __restrict__ hs, const float* __restrict__ wfc,
                       const float* __restrict__ wsig) {
    const int bid = blockIdx.x;
    const int t = threadIdx.x;
    if (bid < 8) {
        const int n = bid;
        const float w0 = wsig[n*5], w1 = wsig[n*5+1], w2 = wsig[n*5+2],
                    w3 = wsig[n*5+3], w4 = wsig[n*5+4];
        // phase 1: score table (log2 domain; b_sigma cancels)
        for (int r = t; r < TT; r += 256) {
            int dxi = r / TW, dyi = r - dxi * TW;
            float dx = (float)(dxi - 47), dy = (float)(dyi - 47);
            g_S[n * TT + r] = (w0*dx + w1*dy + w2*dx*dx + w3*dy*dy + w4*dx*dy) * LOG2E;
        }
        __syncthreads();
        // phase 2: sliding max over dy (window 48)
        for (int o = t; o < TW * HH; o += 256) {
            int dxi = o / HH, j = o - dxi * HH;
            const float* row = g_S + n * TT + dxi * TW + (47 - j);
            float m = -1e30f;
            #pragma unroll 8
            for (int l = 0; l < HH; l++) m = fmaxf(m, row[l]);
            g_cm[n * TW * HH + o] = m;
        }
        __syncthreads();
        // phase 3: sliding max over dx
        for (int o = t; o < NQ; o += 256) {
            int i = o / HH, j = o - i * HH;
            float m = -1e30f;
            #pragma unroll 8
            for (int k = 0; k < WW; k++)
                m = fmaxf(m, g_cm[(n * TW + (k - i + 47)) * HH + j]);
            g_M[n * NQ + o] = m;
        }
    } else if (bid < 8 + WWB) {
        int o = (bid - 8) * 256 + t;
        if (o >= NWW) return;
        int eo = o >> 9, f = o & 511;
        int n = f >> 6, e = f & 63;
        float v = wfc[eo * CC + e * NHD + n];
        __half h = __float2half(v);
        g_Wth[o] = h;
        g_Wtl[o] = __float2half(v - __half2float(h));
    } else {
        // X word index o: [g 64][kx 48][ks 3][lane 32][word 2]
        int o = (bid - 8 - WWB) * 256 + t;
        int word = o & 1;
        int lane = (o >> 1) & 31;
        int t2 = o >> 6;
        int ks = t2 % 3;
        int t3 = t2 / 3;
        int kx = t3 % 48;
        int g  = t3 / 48;
        int n8 = lane >> 2;
        int kk0 = word * 8 + (lane & 3) * 2;
        int c = g * 8 + n8;
        int b = c >> 6, e = c & 63;
        int k = kx * 48 + ks * 16 + kk0;
        float x0 = hs[(b * NQ + k) * EE + e];
        float x1 = hs[(b * NQ + k + 1) * EE + e];
        __half2 h = __floats2half2_rn(x0, x1);
        ((uint32_t*)g_Xbh4)[o] = *(uint32_t*)&h;
    }
}

// ---------------------------------------------------------------------------
// Dynamic smem layout (bytes)
#define SM_STAB 0                 // 51*95*4 = 19380
#define SM_Z    19392             // 128*4 = 512
#define SM_KEEP 19904             // keep[48] | list[48] @+64 | cnt @+128
#define SM_BUF  20480
#define BUFSZ   36864             // Ah 12K | Bh 24K
#define OFF_BH  12288
#define SMEM_TOTAL (SM_BUF + 2 * BUFSZ)   // 94208

// mma.sync fp16 attention GEMM with Gaussian row skipping.
// Block = (q-tile 128, head, col-half 256), 256 threads.
__global__ __launch_bounds__(256, 1) void k_attn() {
    extern __shared__ char smem[];
    const uint32_t sb = smem_u32(smem);
    const int t = threadIdx.x;
    const int w = t >> 5, l = t & 31;
    const int q0 = blockIdx.x * QT;
    const int n  = blockIdx.y;
    const int chalf = blockIdx.z;
    const int i0 = q0 / HH;
    const int d0 = 44 - i0;

    // stage 51-row score-table slice
    float* Stab = (float*)(smem + SM_STAB);
    for (int idx = t; idx < 51 * TW; idx += 256) {
        int r = idx / TW, c = idx - r * TW;
        int dxi = r + d0;
        Stab[idx] = (dxi >= 0 && dxi < TW) ? g_S[n * TT + dxi * TW + c] : -1e30f;
    }

    // ---- row-skip mask ----
    unsigned char* keep = (unsigned char*)(smem + SM_KEEP);
    unsigned char* list = keep + 64;
    int* pcnt = (int*)(keep + 128);
    if (t < 48) keep[t] = 0;
    __syncthreads();
    {
        const int qq = t & 127, hf = t >> 7;
        const int qg2 = q0 + qq;
        const int qi2 = qg2 / HH, qj2 = qg2 - qi2 * HH;
        const float M2x = g_M[n * NQ + qg2];
        const float* cmb = g_cm + ((size_t)(n * TW + 47 - qi2)) * HH + qj2;
        #pragma unroll 4
        for (int kx = hf * 24; kx < hf * 24 + 24; kx++)
            if (cmb[(size_t)kx * HH] - M2x > SKIP_THRESH) keep[kx] = 1;
    }
    __syncthreads();
    if (t == 0) {
        int c2 = 0;
        #pragma unroll 8
        for (int kx = 0; kx < 48; kx++) if (keep[kx]) list[c2++] = kx;
        *pcnt = c2;
    }
    __syncthreads();
    const int cnt = *pcnt;

    // producer constants
    const int r0 = w * 16 + (l >> 2);
    const int r1 = r0 + 8;
    const int qa = q0 + r0, qb = q0 + r1;
    const int qi0 = qa / HH, qj0 = qa - qi0 * HH;
    const int qi1 = qb / HH, qj1 = qb - qi1 * HH;
    const float* Sq0 = Stab + (47 - qi0 - d0) * TW + (47 - qj0);
    const float* Sq1 = Stab + (47 - qi1 - d0) * TW + (47 - qj1);
    const float M20 = g_M[n * NQ + qa];
    const float M21 = g_M[n * NQ + qb];
    float z0 = 0.f, z1 = 0.f;
    const int kbase = (l & 3) * 2;

    const int seg = t >> 3, uu = t & 7;
    const char* srcH = (const char*)g_Xbh4 + ((size_t)(chalf * 32 + seg) * 48) * 768;

    float acc[4][8][4];
    #pragma unroll
    for (int m = 0; m < 4; m++)
        #pragma unroll
        for (int nn = 0; nn < 8; nn++)
            #pragma unroll
            for (int cdx = 0; cdx < 4; cdx++) acc[m][nn][cdx] = 0.f;

    const int wm = w >> 2, wn = w & 3;

    auto produce = [&](int kx, int buf) {
        char* Ah = smem + SM_BUF + buf * BUFSZ;
        const int kxTW = kx * TW;
        #pragma unroll
        for (int ks = 0; ks < 3; ks++) {
            const int ky = ks * 16 + kbase;
            float pa0 = fexp2(Sq0[kxTW + ky]     - M20);
            float pa1 = fexp2(Sq0[kxTW + ky + 1] - M20);
            float pa8 = fexp2(Sq0[kxTW + ky + 8] - M20);
            float pa9 = fexp2(Sq0[kxTW + ky + 9] - M20);
            float pb0 = fexp2(Sq1[kxTW + ky]     - M21);
            float pb1 = fexp2(Sq1[kxTW + ky + 1] - M21);
            float pb8 = fexp2(Sq1[kxTW + ky + 8] - M21);
            float pb9 = fexp2(Sq1[kxTW + ky + 9] - M21);
            z0 += pa0 + pa1 + pa8 + pa9;
            z1 += pb0 + pb1 + pb8 + pb9;
            __half2 h0 = __floats2half2_rn(pa0, pa1);
            __half2 h1 = __floats2half2_rn(pb0, pb1);
            __half2 h2 = __floats2half2_rn(pa8, pa9);
            __half2 h3 = __floats2half2_rn(pb8, pb9);
            const uint32_t off = (uint32_t)(((w * 3 + ks) * 32 + l) * 16);
            *(uint4*)(Ah + off) = make_uint4(*(uint32_t*)&h0, *(uint32_t*)&h1,
                                             *(uint32_t*)&h2, *(uint32_t*)&h3);
        }
        const uint32_t dBh = sb + SM_BUF + buf * BUFSZ + OFF_BH + seg * 768;
        const char* sH = srcH + (size_t)kx * 768;
        #pragma unroll
        for (int i = 0; i < 6; i++) {
            int u16 = (uu + i * 8) * 16;
            cpa16(dBh + u16, sH + u16);
        }
        asm volatile("cp.async.commit_group;" ::: "memory");
    };

    produce(list[0], 0);

    for (int ic = 0; ic < cnt; ic++) {
        const int buf = ic & 1;
        if (ic + 1 < cnt) {
            produce(list[ic + 1], buf ^ 1);
            asm volatile("cp.async.wait_group 1;" ::: "memory");
        } else {
            asm volatile("cp.async.wait_group 0;" ::: "memory");
        }
        __syncthreads();

        const uint4* AhP = (const uint4*)(smem + SM_BUF + buf * BUFSZ);
        const uint2* BhP = (const uint2*)(smem + SM_BUF + buf * BUFSZ + OFF_BH);

        #pragma unroll
        for (int ks = 0; ks < 3; ks++) {
            uint4 ah[4];
            #pragma unroll
            for (int m = 0; m < 4; m++)
                ah[m] = AhP[((wm * 4 + m) * 3 + ks) * 32 + l];
            uint2 bh[8];
            #pragma unroll
            for (int nn = 0; nn < 8; nn++)
                bh[nn] = BhP[((wn * 8 + nn) * 3 + ks) * 32 + l];
            #pragma unroll
            for (int m = 0; m < 4; m++)
                #pragma unroll
                for (int nn = 0; nn < 8; nn++)
                    mma16816h(acc[m][nn], ah[m], bh[nn]);
        }
        __syncthreads();
    }

    z0 += __shfl_xor_sync(0xFFFFFFFFu, z0, 1);
    z0 += __shfl_xor_sync(0xFFFFFFFFu, z0, 2);
    z1 += __shfl_xor_sync(0xFFFFFFFFu, z1, 1);
    z1 += __shfl_xor_sync(0xFFFFFFFFu, z1, 2);
    float* sZ = (float*)(smem + SM_Z);
    if ((l & 3) == 0) { sZ[r0] = z0; sZ[r1] = z1; }
    __syncthreads();

    // epilogue: scale by 1/Z, store fp16 to g_Upk[q][b][n*64+e]
    const int bcol = chalf * 4 + wn;
    #pragma unroll
    for (int m = 0; m < 4; m++) {
        const int rowa = wm * 64 + m * 16 + (l >> 2);
        const float rza = 1.0f / sZ[rowa];
        const float rzb = 1.0f / sZ[rowa + 8];
        __half* dsta = g_Upk + (size_t)(q0 + rowa) * (BB * NHD * EE) + bcol * (NHD * EE) + n * EE;
        __half* dstb = dsta + (size_t)8 * (BB * NHD * EE);
        #pragma unroll
        for (int nn = 0; nn < 8; nn++) {
            const int e = nn * 8 + (l & 3) * 2;
            __half2 va = __floats2half2_rn(acc[m][nn][0] * rza, acc[m][nn][1] * rza);
            __half2 vb = __floats2half2_rn(acc[m][nn][2] * rzb, acc[m][nn][3] * rzb);
            *(__half2*)(dsta + e) = va;
            *(__half2*)(dstb + e) = vb;
        }
    }
}

// ---------------------------------------------------------------------------
// Final projection via fp16 mma (unchanged).
__global__ __launch_bounds__(256) void k_proj(const float* __restrict__ bfc,
                                              float* __restrict__ out) {
    __shared__ __half As[128][72];
    __shared__ __half Whs[64][72];
    __shared__ __half Wls[64][72];
    const int t = threadIdx.x;
    const int w = t >> 5, l = t & 31;
    const int q0 = blockIdx.x * 128;
    const int b  = blockIdx.y;
    const int wm = w >> 1, wn = w & 1;

    float acc[2][4][4];
    #pragma unroll
    for (int m = 0; m < 2; m++)
        #pragma unroll
        for (int nt = 0; nt < 4; nt++)
            #pragma unroll
            for (int c = 0; c < 4; c++) acc[m][nt][c] = 0.f;

    for (int fck = 0; fck < 8; fck++) {
        __syncthreads();
        #pragma unroll
        for (int i = 0; i < 4; i++) {
            int idx = t * 4 + i;
            int row = idx >> 3, u = idx & 7;
            uint4 v = *(const uint4*)(g_Upk + (size_t)(q0 + row) * 4096 + b * 512 + fck * 64 + u * 8);
            *(uint4*)(&As[row][u * 8]) = v;
        }
        #pragma unroll
        for (int i = 0; i < 2; i++) {
            int idx = t * 2 + i;
            int eo = idx >> 3, u = idx & 7;
            uint4 vh = *(const uint4*)(g_Wth + eo * 512 + fck * 64 + u * 8);
            uint4 vl = *(const uint4*)(g_Wtl + eo * 512 + fck * 64 + u * 8);
            *(uint4*)(&Whs[eo][u * 8]) = vh;
            *(uint4*)(&Wls[eo][u * 8]) = vl;
        }
        __syncthreads();

        #pragma unroll
        for (int ks = 0; ks < 4; ks++) {
            const int kb = ks * 16;
            uint4 a[2];
            #pragma unroll
            for (int m = 0; m < 2; m++) {
                const int row = wm * 32 + m * 16 + (l >> 2);
                a[m].x = *(const uint32_t*)(&As[row][kb + (l & 3) * 2]);
                a[m].y = *(const uint32_t*)(&As[row + 8][kb + (l & 3) * 2]);
                a[m].z = *(const uint32_t*)(&As[row][kb + 8 + (l & 3) * 2]);
                a[m].w = *(const uint32_t*)(&As[row + 8][kb + 8 + (l & 3) * 2]);
            }
            #pragma unroll
            for (int nt = 0; nt < 4; nt++) {
                const int eo = wn * 32 + nt * 8 + (l >> 2);
                uint2 bh, bl;
                bh.x = *(const uint32_t*)(&Whs[eo][kb + (l & 3) * 2]);
                bh.y = *(const uint32_t*)(&Whs[eo][kb + 8 + (l & 3) * 2]);
                bl.x = *(const uint32_t*)(&Wls[eo][kb + (l & 3) * 2]);
                bl.y = *(const uint32_t*)(&Wls[eo][kb + 8 + (l & 3) * 2]);
                #pragma unroll
                for (int m = 0; m < 2; m++) {
                    mma16816h(acc[m][nt], a[m], bh);
                    mma16816h(acc[m][nt], a[m], bl);
                }
            }
        }
    }

    #pragma unroll
    for (int m = 0; m < 2; m++) {
        const int row = wm * 32 + m * 16 + (l >> 2);
        #pragma unroll
        for (int nt = 0; nt < 4; nt++) {
            const int eo = wn * 32 + nt * 8 + (l & 3) * 2;
            float2 v0 = make_float2(acc[m][nt][0] + bfc[eo], acc[m][nt][1] + bfc[eo + 1]);
            float2 v1 = make_float2(acc[m][nt][2] + bfc[eo], acc[m][nt][3] + bfc[eo + 1]);
            *(float2*)(out + (size_t)(b * NQ + q0 + row) * EE + eo) = v0;
            *(float2*)(out + (size_t)(b * NQ + q0 + row + 8) * EE + eo) = v1;
        }
    }
}

// ---------------------------------------------------------------------------
extern "C" void kernel_launch(void* const* d_in, const int* in_sizes, int n_in,
                              void* d_out, int out_size) {
    const float* hs   = (const float*)d_in[0];
    const float* wsig = (const float*)d_in[3];
    const float* wfc  = (const float*)d_in[5];
    const float* bfc  = (const float*)d_in[6];
    float* out = (float*)d_out;

    cudaFuncSetAttribute(k_attn, cudaFuncAttributeMaxDynamicSharedMemorySize, SMEM_TOTAL);

    k_prep<<<8 + WWB + XWB, 256>>>(hs, wfc, wsig);   // 2440 blocks, one launch

    dim3 ga(NQ / QT, NHD, 2);   // (18, 8, 2)
    k_attn<<<ga, 256, SMEM_TOTAL>>>();

    dim3 gp(NQ / 128, BB);      // (18, 8)
    k_proj<<<gp, 256>>>(bfc, out);
}

// round 13
// speedup vs baseline: 1.0236x; 1.0236x over previous
#include <cuda_runtime.h>
#include <cuda_fp16.h>
#include <cstdint>

#define WW 48
#define HH 48
#define NQ 2304
#define NHD 8
#define EE 64
#define BB 8
#define CC 512
#define TW 95
#define TT (TW*TW)
#define LOG2E 1.4426950408889634f

#define QT 128            // M per block
#define NCOL 256          // N per block
#define NW32 (CC*NQ/2)    // b32 words in X operand (589824)
#define NWW (EE*CC)       // wsplit items (32768)
#define WWB ((NWW+255)/256) // 128 w-split blocks
#define XPB (BB*48)       // 384 x-pack blocks (b, kx)
#define SKIP_THRESH (-18.0f)

// ---- device scratch ----
__device__ float g_S[NHD * TT];
__device__ float g_cm[NHD * TW * HH];
__device__ float g_M[NHD * NQ];
__device__ __align__(256) uint4 g_Xbh4[NW32 / 4];   // X fp16, fragment-major [g][kx][ks][lane][word]
__device__ __align__(16) __half g_Upk[NQ * BB * NHD * EE];  // U fp16: [q][b][n*64+e]
__device__ __align__(16) __half g_Wth[EE * CC];     // W^T hi fp16: [eo][f=n*64+e]
__device__ __align__(16) __half g_Wtl[EE * CC];     // W^T lo

__device__ __forceinline__ float fexp2(float x) {
    float y; asm("ex2.approx.ftz.f32 %0, %1;" : "=f"(y) : "f"(x)); return y;
}
__device__ __forceinline__ uint32_t smem_u32(const void* p) {
    uint32_t a;
    asm("{ .reg .u64 t; cvta.to.shared.u64 t, %1; cvt.u32.u64 %0, t; }" : "=r"(a) : "l"(p));
    return a;
}
__device__ __forceinline__ void cpa16(uint32_t dst, const void* src) {
    asm volatile("cp.async.cg.shared.global [%0], [%1], 16;" :: "r"(dst), "l"(src));
}
__device__ __forceinline__ void mma16816h(float* c, const uint4& a, const uint2& b) {
    asm volatile(
        "mma.sync.aligned.m16n8k16.row.col.f32.f16.f16.f32 "
        "{%0,%1,%2,%3}, {%4,%5,%6,%7}, {%8,%9}, {%0,%1,%2,%3};"
        : "+f"(c[0]), "+f"(c[1]), "+f"(c[2]), "+f"(c[3])
        : "r"(a.x), "r"(a.y), "r"(a.z), "r"(a.w), "r"(b.x), "r"(b.y));
}

// ---------------------------------------------------------------------------
// ONE fused prep kernel.
// blocks [0,8):           per-head table -> colmax -> rowmax (phased)
// blocks [8, 8+WWB):      W^T split hi/lo
// blocks [8+WWB, +XPB):   X fragment-pack via coalesced smem staging
__global__ void k_prep(const float* __restrict__ hs, const float* __restrict__ wfc,
                       const float* __restrict__ wsig) {
    __shared__ float xs[48 * 64];      // 12KB staging (x-pack blocks only)
    const int bid = blockIdx.x;
    const int t = threadIdx.x;
    if (bid < 8) {
        const int n = bid;
        const float w0 = wsig[n*5], w1 = wsig[n*5+1], w2 = wsig[n*5+2],
                    w3 = wsig[n*5+3], w4 = wsig[n*5+4];
        for (int r = t; r < TT; r += 256) {
            int dxi = r / TW, dyi = r - dxi * TW;
            float dx = (float)(dxi - 47), dy = (float)(dyi - 47);
            g_S[n * TT + r] = (w0*dx + w1*dy + w2*dx*dx + w3*dy*dy + w4*dx*dy) * LOG2E;
        }
        __syncthreads();
        for (int o = t; o < TW * HH; o += 256) {
            int dxi = o / HH, j = o - dxi * HH;
            const float* row = g_S + n * TT + dxi * TW + (47 - j);
            float m = -1e30f;
            #pragma unroll 8
            for (int l = 0; l < HH; l++) m = fmaxf(m, row[l]);
            g_cm[n * TW * HH + o] = m;
        }
        __syncthreads();
        for (int o = t; o < NQ; o += 256) {
            int i = o / HH, j = o - i * HH;
            float m = -1e30f;
            #pragma unroll 8
            for (int k = 0; k < WW; k++)
                m = fmaxf(m, g_cm[(n * TW + (k - i + 47)) * HH + j]);
            g_M[n * NQ + o] = m;
        }
    } else if (bid < 8 + WWB) {
        int o = (bid - 8) * 256 + t;
        if (o >= NWW) return;
        int eo = o >> 9, f = o & 511;
        int n = f >> 6, e = f & 63;
        float v = wfc[eo * CC + e * NHD + n];
        __half h = __float2half(v);
        g_Wth[o] = h;
        g_Wtl[o] = __float2half(v - __half2float(h));
    } else {
        // x-pack: block = (b, kx). Stage hs[b][kx*48 .. +48][0..64) coalesced,
        // then emit the SAME fragment words as before from smem.
        const int id2 = bid - 8 - WWB;
        const int b  = id2 / 48;
        const int kx = id2 - b * 48;
        const float* src = hs + ((size_t)b * NQ + kx * 48) * EE;
        #pragma unroll
        for (int i = 0; i < 12; i++)
            xs[t + i * 256] = src[t + i * 256];
        __syncthreads();
        // 1536 output words: o2 = [gl 8][ks 3][lane 32][word 2]
        #pragma unroll
        for (int i = 0; i < 6; i++) {
            int o2 = t + i * 256;
            int word = o2 & 1;
            int lane = (o2 >> 1) & 31;
            int ks   = (o2 >> 6) % 3;
            int gl   = (o2 >> 6) / 3;
            int n8   = lane >> 2;
            int e    = gl * 8 + n8;
            int kl   = ks * 16 + word * 8 + (lane & 3) * 2;
            float x0 = xs[kl * 64 + e];
            float x1 = xs[(kl + 1) * 64 + e];
            __half2 h = __floats2half2_rn(x0, x1);
            int g = b * 8 + gl;
            int o = ((g * 48 + kx) * 3 + ks) * 64 + lane * 2 + word;
            ((uint32_t*)g_Xbh4)[o] = *(uint32_t*)&h;
        }
    }
}

// ---------------------------------------------------------------------------
// Dynamic smem layout (bytes)
#define SM_STAB 0                 // 51*95*4 = 19380
#define SM_Z    19392             // 128*4 = 512
#define SM_KEEP 19904             // keep[48] | list[48] @+64 | cnt @+128
#define SM_BUF  20480
#define BUFSZ   36864             // Ah 12K | Bh 24K
#define OFF_BH  12288
#define SMEM_TOTAL (SM_BUF + 2 * BUFSZ)   // 94208

// mma.sync fp16 attention GEMM, row-skipped, producer pipelined under MMA.
// Block = (q-tile 128, head, col-half 256), 256 threads.
__global__ __launch_bounds__(256, 1) void k_attn() {
    extern __shared__ char smem[];
    const uint32_t sb = smem_u32(smem);
    const int t = threadIdx.x;
    const int w = t >> 5, l = t & 31;
    const int q0 = blockIdx.x * QT;
    const int n  = blockIdx.y;
    const int chalf = blockIdx.z;
    const int i0 = q0 / HH;
    const int d0 = 44 - i0;

    // stage 51-row score-table slice
    float* Stab = (float*)(smem + SM_STAB);
    for (int idx = t; idx < 51 * TW; idx += 256) {
        int r = idx / TW, c = idx - r * TW;
        int dxi = r + d0;
        Stab[idx] = (dxi >= 0 && dxi < TW) ? g_S[n * TT + dxi * TW + c] : -1e30f;
    }

    // ---- row-skip mask ----
    unsigned char* keep = (unsigned char*)(smem + SM_KEEP);
    unsigned char* list = keep + 64;
    int* pcnt = (int*)(keep + 128);
    if (t < 48) keep[t] = 0;
    __syncthreads();
    {
        const int qq = t & 127, hf = t >> 7;
        const int qg2 = q0 + qq;
        const int qi2 = qg2 / HH, qj2 = qg2 - qi2 * HH;
        const float M2x = g_M[n * NQ + qg2];
        const float* cmb = g_cm + ((size_t)(n * TW + 47 - qi2)) * HH + qj2;
        #pragma unroll 4
        for (int kx = hf * 24; kx < hf * 24 + 24; kx++)
            if (cmb[(size_t)kx * HH] - M2x > SKIP_THRESH) keep[kx] = 1;
    }
    __syncthreads();
    if (t == 0) {
        int c2 = 0;
        #pragma unroll 8
        for (int kx = 0; kx < 48; kx++) if (keep[kx]) list[c2++] = kx;
        *pcnt = c2;
    }
    __syncthreads();
    const int cnt = *pcnt;

    // producer constants
    const int r0 = w * 16 + (l >> 2);
    const int r1 = r0 + 8;
    const int qa = q0 + r0, qb = q0 + r1;
    const int qi0 = qa / HH, qj0 = qa - qi0 * HH;
    const int qi1 = qb / HH, qj1 = qb - qi1 * HH;
    const float* Sq0 = Stab + (47 - qi0 - d0) * TW + (47 - qj0);
    const float* Sq1 = Stab + (47 - qi1 - d0) * TW + (47 - qj1);
    const float M20 = g_M[n * NQ + qa];
    const float M21 = g_M[n * NQ + qb];
    float z0 = 0.f, z1 = 0.f;
    const int kbase = (l & 3) * 2;

    const int seg = t >> 3, uu = t & 7;
    const char* srcH = (const char*)g_Xbh4 + ((size_t)(chalf * 32 + seg) * 48) * 768;

    float acc[4][8][4];
    #pragma unroll
    for (int m = 0; m < 4; m++)
        #pragma unroll
        for (int nn = 0; nn < 8; nn++)
            #pragma unroll
            for (int cdx = 0; cdx < 4; cdx++) acc[m][nn][cdx] = 0.f;

    const int wm = w >> 2, wn = w & 3;

    // A producer: exp + pack + STS only (no cp.async)
    auto produceA = [&](int kx, int buf) {
        char* Ah = smem + SM_BUF + buf * BUFSZ;
        const int kxTW = kx * TW;
        #pragma unroll
        for (int ks = 0; ks < 3; ks++) {
            const int ky = ks * 16 + kbase;
            float pa0 = fexp2(Sq0[kxTW + ky]     - M20);
            float pa1 = fexp2(Sq0[kxTW + ky + 1] - M20);
            float pa8 = fexp2(Sq0[kxTW + ky + 8] - M20);
            float pa9 = fexp2(Sq0[kxTW + ky + 9] - M20);
            float pb0 = fexp2(Sq1[kxTW + ky]     - M21);
            float pb1 = fexp2(Sq1[kxTW + ky + 1] - M21);
            float pb8 = fexp2(Sq1[kxTW + ky + 8] - M21);
            float pb9 = fexp2(Sq1[kxTW + ky + 9] - M21);
            z0 += pa0 + pa1 + pa8 + pa9;
            z1 += pb0 + pb1 + pb8 + pb9;
            __half2 h0 = __floats2half2_rn(pa0, pa1);
            __half2 h1 = __floats2half2_rn(pb0, pb1);
            __half2 h2 = __floats2half2_rn(pa8, pa9);
            __half2 h3 = __floats2half2_rn(pb8, pb9);
            const uint32_t off = (uint32_t)(((w * 3 + ks) * 32 + l) * 16);
            *(uint4*)(Ah + off) = make_uint4(*(uint32_t*)&h0, *(uint32_t*)&h1,
                                             *(uint32_t*)&h2, *(uint32_t*)&h3);
        }
    };
    // B stage: cp.async + commit
    auto issueB = [&](int kx, int buf) {
        const uint32_t dBh = sb + SM_BUF + buf * BUFSZ + OFF_BH + seg * 768;
        const char* sH = srcH + (size_t)kx * 768;
        #pragma unroll
        for (int i = 0; i < 6; i++) {
            int u16 = (uu + i * 8) * 16;
            cpa16(dBh + u16, sH + u16);
        }
        asm volatile("cp.async.commit_group;" ::: "memory");
    };
    // one ks-step of MMA on buffer buf
    auto mmaKS = [&](int ks, int buf) {
        const uint4* AhP = (const uint4*)(smem + SM_BUF + buf * BUFSZ);
        const uint2* BhP = (const uint2*)(smem + SM_BUF + buf * BUFSZ + OFF_BH);
        uint4 ah[4];
        #pragma unroll
        for (int m = 0; m < 4; m++)
            ah[m] = AhP[((wm * 4 + m) * 3 + ks) * 32 + l];
        uint2 bh[8];
        #pragma unroll
        for (int nn = 0; nn < 8; nn++)
            bh[nn] = BhP[((wn * 8 + nn) * 3 + ks) * 32 + l];
        #pragma unroll
        for (int m = 0; m < 4; m++)
            #pragma unroll
            for (int nn = 0; nn < 8; nn++)
                mma16816h(acc[m][nn], ah[m], bh[nn]);
    };

    // prologue: fill buffer 0 for the first kept chunk
    produceA(list[0], 0);
    issueB(list[0], 0);

    for (int ic = 0; ic < cnt; ic++) {
        const int buf = ic & 1;
        const bool more = (ic + 1 < cnt);
        if (more) issueB(list[ic + 1], buf ^ 1);   // gets a full iter of flight
        if (more) asm volatile("cp.async.wait_group 1;" ::: "memory");
        else      asm volatile("cp.async.wait_group 0;" ::: "memory");
        __syncthreads();            // B(ic)+A(ic) visible to all
        mmaKS(0, buf);
        if (more) produceA(list[ic + 1], buf ^ 1); // MUFU overlaps HMMA across warps
        mmaKS(1, buf);
        mmaKS(2, buf);
        __syncthreads();            // done reading buf; A(ic+1) writes fenced
    }

    z0 += __shfl_xor_sync(0xFFFFFFFFu, z0, 1);
    z0 += __shfl_xor_sync(0xFFFFFFFFu, z0, 2);
    z1 += __shfl_xor_sync(0xFFFFFFFFu, z1, 1);
    z1 += __shfl_xor_sync(0xFFFFFFFFu, z1, 2);
    float* sZ = (float*)(smem + SM_Z);
    if ((l & 3) == 0) { sZ[r0] = z0; sZ[r1] = z1; }
    __syncthreads();

    // epilogue: scale by 1/Z, store fp16 to g_Upk[q][b][n*64+e]
    const int bcol = chalf * 4 + wn;
    #pragma unroll
    for (int m = 0; m < 4; m++) {
        const int rowa = wm * 64 + m * 16 + (l >> 2);
        const float rza = 1.0f / sZ[rowa];
        const float rzb = 1.0f / sZ[rowa + 8];
        __half* dsta = g_Upk + (size_t)(q0 + rowa) * (BB * NHD * EE) + bcol * (NHD * EE) + n * EE;
        __half* dstb = dsta + (size_t)8 * (BB * NHD * EE);
        #pragma unroll
        for (int nn = 0; nn < 8; nn++) {
            const int e = nn * 8 + (l & 3) * 2;
            __half2 va = __floats2half2_rn(acc[m][nn][0] * rza, acc[m][nn][1] * rza);
            __half2 vb = __floats2half2_rn(acc[m][nn][2] * rzb, acc[m][nn][3] * rzb);
            *(__half2*)(dsta + e) = va;
            *(__half2*)(dstb + e) = vb;
        }
    }
}

// ---------------------------------------------------------------------------
// Final projection via fp16 mma (unchanged).
__global__ __launch_bounds__(256) void k_proj(const float* __restrict__ bfc,
                                              float* __restrict__ out) {
    __shared__ __half As[128][72];
    __shared__ __half Whs[64][72];
    __shared__ __half Wls[64][72];
    const int t = threadIdx.x;
    const int w = t >> 5, l = t & 31;
    const int q0 = blockIdx.x * 128;
    const int b  = blockIdx.y;
    const int wm = w >> 1, wn = w & 1;

    float acc[2][4][4];
    #pragma unroll
    for (int m = 0; m < 2; m++)
        #pragma unroll
        for (int nt = 0; nt < 4; nt++)
            #pragma unroll
            for (int c = 0; c < 4; c++) acc[m][nt][c] = 0.f;

    for (int fck = 0; fck < 8; fck++) {
        __syncthreads();
        #pragma unroll
        for (int i = 0; i < 4; i++) {
            int idx = t * 4 + i;
            int row = idx >> 3, u = idx & 7;
            uint4 v = *(const uint4*)(g_Upk + (size_t)(q0 + row) * 4096 + b * 512 + fck * 64 + u * 8);
            *(uint4*)(&As[row][u * 8]) = v;
        }
        #pragma unroll
        for (int i = 0; i < 2; i++) {
            int idx = t * 2 + i;
            int eo = idx >> 3, u = idx & 7;
            uint4 vh = *(const uint4*)(g_Wth + eo * 512 + fck * 64 + u * 8);
            uint4 vl = *(const uint4*)(g_Wtl + eo * 512 + fck * 64 + u * 8);
            *(uint4*)(&Whs[eo][u * 8]) = vh;
            *(uint4*)(&Wls[eo][u * 8]) = vl;
        }
        __syncthreads();

        #pragma unroll
        for (int ks = 0; ks < 4; ks++) {
            const int kb = ks * 16;
            uint4 a[2];
            #pragma unroll
            for (int m = 0; m < 2; m++) {
                const int row = wm * 32 + m * 16 + (l >> 2);
                a[m].x = *(const uint32_t*)(&As[row][kb + (l & 3) * 2]);
                a[m].y = *(const uint32_t*)(&As[row + 8][kb + (l & 3) * 2]);
                a[m].z = *(const uint32_t*)(&As[row][kb + 8 + (l & 3) * 2]);
                a[m].w = *(const uint32_t*)(&As[row + 8][kb + 8 + (l & 3) * 2]);
            }
            #pragma unroll
            for (int nt = 0; nt < 4; nt++) {
                const int eo = wn * 32 + nt * 8 + (l >> 2);
                uint2 bh, bl;
                bh.x = *(const uint32_t*)(&Whs[eo][kb + (l & 3) * 2]);
                bh.y = *(const uint32_t*)(&Whs[eo][kb + 8 + (l & 3) * 2]);
                bl.x = *(const uint32_t*)(&Wls[eo][kb + (l & 3) * 2]);
                bl.y = *(const uint32_t*)(&Wls[eo][kb + 8 + (l & 3) * 2]);
                #pragma unroll
                for (int m = 0; m < 2; m++) {
                    mma16816h(acc[m][nt], a[m], bh);
                    mma16816h(acc[m][nt], a[m], bl);
                }
            }
        }
    }

    #pragma unroll
    for (int m = 0; m < 2; m++) {
        const int row = wm * 32 + m * 16 + (l >> 2);
        #pragma unroll
        for (int nt = 0; nt < 4; nt++) {
            const int eo = wn * 32 + nt * 8 + (l & 3) * 2;
            float2 v0 = make_float2(acc[m][nt][0] + bfc[eo], acc[m][nt][1] + bfc[eo + 1]);
            float2 v1 = make_float2(acc[m][nt][2] + bfc[eo], acc[m][nt][3] + bfc[eo + 1]);
            *(float2*)(out + (size_t)(b * NQ + q0 + row) * EE + eo) = v0;
            *(float2*)(out + (size_t)(b * NQ + q0 + row + 8) * EE + eo) = v1;
        }
    }
}

// ---------------------------------------------------------------------------
extern "C" void kernel_launch(void* const* d_in, const int* in_sizes, int n_in,
                              void* d_out, int out_size) {
    const float* hs   = (const float*)d_in[0];
    const float* wsig = (const float*)d_in[3];
    const float* wfc  = (const float*)d_in[5];
    const float* bfc  = (const float*)d_in[6];
    float* out = (float*)d_out;

    cudaFuncSetAttribute(k_attn, cudaFuncAttributeMaxDynamicSharedMemorySize, SMEM_TOTAL);

    k_prep<<<8 + WWB + XPB, 256>>>(hs, wfc, wsig);   // 520 blocks, one launch

    dim3 ga(NQ / QT, NHD, 2);   // (18, 8, 2)
    k_attn<<<ga, 256, SMEM_TOTAL>>>();

    dim3 gp(NQ / 128, BB);      // (18, 8)
    k_proj<<<gp, 256>>>(bfc, out);
}

// round 14
// speedup vs baseline: 1.1860x; 1.1587x over previous
#include <cuda_runtime.h>
#include <cuda_fp16.h>
#include <cstdint>

#define WW 48
#define HH 48
#define NQ 2304
#define NHD 8
#define EE 64
#define BB 8
#define CC 512
#define TW 95
#define TT (TW*TW)
#define LOG2E 1.4426950408889634f

#define QT 64             // M per block (halved for occupancy 2)
#define NCOL 256          // N per block
#define NW32 (CC*NQ/2)    // b32 words in X operand (589824)
#define NWW (EE*CC)       // wsplit items (32768)
#define WWB ((NWW+255)/256) // 128 w-split blocks
#define XPB (BB*48)       // 384 x-pack blocks (b, kx)
#define SKIP_THRESH (-18.0f)

// ---- device scratch ----
__device__ float g_S[NHD * TT];
__device__ float g_cm[NHD * TW * HH];
__device__ float g_M[NHD * NQ];
__device__ __align__(256) uint4 g_Xbh4[NW32 / 4];   // X fp16, fragment-major [g][kx][ks][lane][word]
__device__ __align__(16) __half g_Upk[NQ * BB * NHD * EE];  // U fp16: [q][b][n*64+e]
__device__ __align__(16) __half g_Wth[EE * CC];     // W^T hi fp16: [eo][f=n*64+e]
__device__ __align__(16) __half g_Wtl[EE * CC];     // W^T lo

__device__ __forceinline__ float fexp2(float x) {
    float y; asm("ex2.approx.ftz.f32 %0, %1;" : "=f"(y) : "f"(x)); return y;
}
__device__ __forceinline__ uint32_t smem_u32(const void* p) {
    uint32_t a;
    asm("{ .reg .u64 t; cvta.to.shared.u64 t, %1; cvt.u32.u64 %0, t; }" : "=r"(a) : "l"(p));
    return a;
}
__device__ __forceinline__ void cpa16(uint32_t dst, const void* src) {
    asm volatile("cp.async.cg.shared.global [%0], [%1], 16;" :: "r"(dst), "l"(src));
}
__device__ __forceinline__ void mma16816h(float* c, const uint4& a, const uint2& b) {
    asm volatile(
        "mma.sync.aligned.m16n8k16.row.col.f32.f16.f16.f32 "
        "{%0,%1,%2,%3}, {%4,%5,%6,%7}, {%8,%9}, {%0,%1,%2,%3};"
        : "+f"(c[0]), "+f"(c[1]), "+f"(c[2]), "+f"(c[3])
        : "r"(a.x), "r"(a.y), "r"(a.z), "r"(a.w), "r"(b.x), "r"(b.y));
}

// ---------------------------------------------------------------------------
// ONE fused prep kernel (unchanged from R13).
__global__ void k_prep(const float* __restrict__ hs, const float* __restrict__ wfc,
                       const float* __restrict__ wsig) {
    __shared__ float xs[48 * 64];
    const int bid = blockIdx.x;
    const int t = threadIdx.x;
    if (bid < 8) {
        const int n = bid;
        const float w0 = wsig[n*5], w1 = wsig[n*5+1], w2 = wsig[n*5+2],
                    w3 = wsig[n*5+3], w4 = wsig[n*5+4];
        for (int r = t; r < TT; r += 256) {
            int dxi = r / TW, dyi = r - dxi * TW;
            float dx = (float)(dxi - 47), dy = (float)(dyi - 47);
            g_S[n * TT + r] = (w0*dx + w1*dy + w2*dx*dx + w3*dy*dy + w4*dx*dy) * LOG2E;
        }
        __syncthreads();
        for (int o = t; o < TW * HH; o += 256) {
            int dxi = o / HH, j = o - dxi * HH;
            const float* row = g_S + n * TT + dxi * TW + (47 - j);
            float m = -1e30f;
            #pragma unroll 8
            for (int l = 0; l < HH; l++) m = fmaxf(m, row[l]);
            g_cm[n * TW * HH + o] = m;
        }
        __syncthreads();
        for (int o = t; o < NQ; o += 256) {
            int i = o / HH, j = o - i * HH;
            float m = -1e30f;
            #pragma unroll 8
            for (int k = 0; k < WW; k++)
                m = fmaxf(m, g_cm[(n * TW + (k - i + 47)) * HH + j]);
            g_M[n * NQ + o] = m;
        }
    } else if (bid < 8 + WWB) {
        int o = (bid - 8) * 256 + t;
        if (o >= NWW) return;
        int eo = o >> 9, f = o & 511;
        int n = f >> 6, e = f & 63;
        float v = wfc[eo * CC + e * NHD + n];
        __half h = __float2half(v);
        g_Wth[o] = h;
        g_Wtl[o] = __float2half(v - __half2float(h));
    } else {
        const int id2 = bid - 8 - WWB;
        const int b  = id2 / 48;
        const int kx = id2 - b * 48;
        const float* src = hs + ((size_t)b * NQ + kx * 48) * EE;
        #pragma unroll
        for (int i = 0; i < 12; i++)
            xs[t + i * 256] = src[t + i * 256];
        __syncthreads();
        #pragma unroll
        for (int i = 0; i < 6; i++) {
            int o2 = t + i * 256;
            int word = o2 & 1;
            int lane = (o2 >> 1) & 31;
            int ks   = (o2 >> 6) % 3;
            int gl   = (o2 >> 6) / 3;
            int n8   = lane >> 2;
            int e    = gl * 8 + n8;
            int kl   = ks * 16 + word * 8 + (lane & 3) * 2;
            float x0 = xs[kl * 64 + e];
            float x1 = xs[(kl + 1) * 64 + e];
            __half2 h = __floats2half2_rn(x0, x1);
            int g = b * 8 + gl;
            int o = ((g * 48 + kx) * 3 + ks) * 64 + lane * 2 + word;
            ((uint32_t*)g_Xbh4)[o] = *(uint32_t*)&h;
        }
    }
}

// ---------------------------------------------------------------------------
// Dynamic smem layout (bytes)
#define SM_STAB 0                 // 49*95*4 = 18620
#define SM_Z    18624             // 64*4 = 256
#define SM_KEEP 18880             // keep[48] | list[48] @+64 | cnt @+128
#define SM_BUF  19072
#define BUFSZ   30720             // Ah 6K | Bh 24K
#define OFF_BH  6144
#define SMEM_TOTAL (SM_BUF + 2 * BUFSZ)   // 80512 -> 2 blocks/SM

// mma.sync fp16 attention GEMM, row-skipped, pipelined, occupancy 2.
// Block = (q-tile 64, head, col-half 256), 256 threads.
__global__ __launch_bounds__(256, 2) void k_attn() {
    extern __shared__ char smem[];
    const uint32_t sb = smem_u32(smem);
    const int t = threadIdx.x;
    const int w = t >> 5, l = t & 31;
    const int q0 = blockIdx.x * QT;
    const int n  = blockIdx.y;
    const int chalf = blockIdx.z;
    const int d0 = 47 - ((q0 + QT - 1) / HH);   // 49-row slice offset

    // stage 49-row score-table slice
    float* Stab = (float*)(smem + SM_STAB);
    for (int idx = t; idx < 49 * TW; idx += 256) {
        int r = idx / TW, c = idx - r * TW;
        int dxi = r + d0;
        Stab[idx] = (dxi >= 0 && dxi < TW) ? g_S[n * TT + dxi * TW + c] : -1e30f;
    }

    // ---- row-skip mask (64 queries, 4 thread-groups x 12 kx) ----
    unsigned char* keep = (unsigned char*)(smem + SM_KEEP);
    unsigned char* list = keep + 64;
    int* pcnt = (int*)(keep + 128);
    if (t < 48) keep[t] = 0;
    __syncthreads();
    {
        const int qq = t & 63, hf = t >> 6;     // hf in [0,4)
        const int qg2 = q0 + qq;
        const int qi2 = qg2 / HH, qj2 = qg2 - qi2 * HH;
        const float M2x = g_M[n * NQ + qg2];
        const float* cmb = g_cm + ((size_t)(n * TW + 47 - qi2)) * HH + qj2;
        #pragma unroll 4
        for (int kx = hf * 12; kx < hf * 12 + 12; kx++)
            if (cmb[(size_t)kx * HH] - M2x > SKIP_THRESH) keep[kx] = 1;
    }
    __syncthreads();
    if (t == 0) {
        int c2 = 0;
        #pragma unroll 8
        for (int kx = 0; kx < 48; kx++) if (keep[kx]) list[c2++] = kx;
        *pcnt = c2;
    }
    __syncthreads();
    const int cnt = *pcnt;

    // producer constants: warp w owns A m-tile mt=w&3; lane rows r0, r0+8
    const int mt = w & 3;
    const int r0 = mt * 16 + (l >> 2);
    const int r1 = r0 + 8;
    const int qa = q0 + r0, qb = q0 + r1;
    const int qi0 = qa / HH, qj0 = qa - qi0 * HH;
    const int qi1 = qb / HH, qj1 = qb - qi1 * HH;
    const float* Sq0 = Stab + (47 - qi0 - d0) * TW + (47 - qj0);
    const float* Sq1 = Stab + (47 - qi1 - d0) * TW + (47 - qj1);
    const float M20 = g_M[n * NQ + qa];
    const float M21 = g_M[n * NQ + qb];
    float z0 = 0.f, z1 = 0.f;
    const int kbase = (l & 3) * 2;

    const int seg = t >> 3, uu = t & 7;
    const char* srcH = (const char*)g_Xbh4 + ((size_t)(chalf * 32 + seg) * 48) * 768;

    float acc[2][8][4];
    #pragma unroll
    for (int m = 0; m < 2; m++)
        #pragma unroll
        for (int nn = 0; nn < 8; nn++)
            #pragma unroll
            for (int cdx = 0; cdx < 4; cdx++) acc[m][nn][cdx] = 0.f;

    const int wm = w >> 2, wn = w & 3;   // consumer: rows wm*32.., cols wn*64..

    // one ks of A production for this warp's m-tile
    auto prodKS = [&](int kx, int buf, int ks) {
        char* Ah = smem + SM_BUF + buf * BUFSZ;
        const int kxTW = kx * TW;
        const int ky = ks * 16 + kbase;
        float pa0 = fexp2(Sq0[kxTW + ky]     - M20);
        float pa1 = fexp2(Sq0[kxTW + ky + 1] - M20);
        float pa8 = fexp2(Sq0[kxTW + ky + 8] - M20);
        float pa9 = fexp2(Sq0[kxTW + ky + 9] - M20);
        float pb0 = fexp2(Sq1[kxTW + ky]     - M21);
        float pb1 = fexp2(Sq1[kxTW + ky + 1] - M21);
        float pb8 = fexp2(Sq1[kxTW + ky + 8] - M21);
        float pb9 = fexp2(Sq1[kxTW + ky + 9] - M21);
        z0 += pa0 + pa1 + pa8 + pa9;
        z1 += pb0 + pb1 + pb8 + pb9;
        __half2 h0 = __floats2half2_rn(pa0, pa1);
        __half2 h1 = __floats2half2_rn(pb0, pb1);
        __half2 h2 = __floats2half2_rn(pa8, pa9);
        __half2 h3 = __floats2half2_rn(pb8, pb9);
        const uint32_t off = (uint32_t)(((mt * 3 + ks) * 32 + l) * 16);
        *(uint4*)(Ah + off) = make_uint4(*(uint32_t*)&h0, *(uint32_t*)&h1,
                                         *(uint32_t*)&h2, *(uint32_t*)&h3);
    };
    // warps 0-3 produce ks {0,2}; warps 4-7 produce ks {1}  (12 tasks total)
    auto produceA = [&](int kx, int buf) {
        if (w < 4) { prodKS(kx, buf, 0); prodKS(kx, buf, 2); }
        else       { prodKS(kx, buf, 1); }
    };
    auto issueB = [&](int kx, int buf) {
        const uint32_t dBh = sb + SM_BUF + buf * BUFSZ + OFF_BH + seg * 768;
        const char* sH = srcH + (size_t)kx * 768;
        #pragma unroll
        for (int i = 0; i < 6; i++) {
            int u16 = (uu + i * 8) * 16;
            cpa16(dBh + u16, sH + u16);
        }
        asm volatile("cp.async.commit_group;" ::: "memory");
    };
    auto mmaKS = [&](int ks, int buf) {
        const uint4* AhP = (const uint4*)(smem + SM_BUF + buf * BUFSZ);
        const uint2* BhP = (const uint2*)(smem + SM_BUF + buf * BUFSZ + OFF_BH);
        uint4 ah[2];
        #pragma unroll
        for (int m = 0; m < 2; m++)
            ah[m] = AhP[((wm * 2 + m) * 3 + ks) * 32 + l];
        uint2 bh[8];
        #pragma unroll
        for (int nn = 0; nn < 8; nn++)
            bh[nn] = BhP[((wn * 8 + nn) * 3 + ks) * 32 + l];
        #pragma unroll
        for (int m = 0; m < 2; m++)
            #pragma unroll
            for (int nn = 0; nn < 8; nn++)
                mma16816h(acc[m][nn], ah[m], bh[nn]);
    };

    produceA(list[0], 0);
    issueB(list[0], 0);

    for (int ic = 0; ic < cnt; ic++) {
        const int buf = ic & 1;
        const bool more = (ic + 1 < cnt);
        if (more) issueB(list[ic + 1], buf ^ 1);
        if (more) asm volatile("cp.async.wait_group 1;" ::: "memory");
        else      asm volatile("cp.async.wait_group 0;" ::: "memory");
        __syncthreads();
        mmaKS(0, buf);
        if (more) produceA(list[ic + 1], buf ^ 1);
        mmaKS(1, buf);
        mmaKS(2, buf);
        __syncthreads();
    }

    // Z: reduce over the 4 lanes sharing l>>2, then merge warp w and w+4
    z0 += __shfl_xor_sync(0xFFFFFFFFu, z0, 1);
    z0 += __shfl_xor_sync(0xFFFFFFFFu, z0, 2);
    z1 += __shfl_xor_sync(0xFFFFFFFFu, z1, 1);
    z1 += __shfl_xor_sync(0xFFFFFFFFu, z1, 2);
    float* sZ = (float*)(smem + SM_Z);
    if (w < 4 && (l & 3) == 0) { sZ[r0] = z0; sZ[r1] = z1; }
    __syncthreads();
    if (w >= 4 && (l & 3) == 0) { sZ[r0] += z0; sZ[r1] += z1; }
    __syncthreads();

    // epilogue: scale by 1/Z, store fp16 to g_Upk[q][b][n*64+e]
    const int bcol = chalf * 4 + wn;
    #pragma unroll
    for (int m = 0; m < 2; m++) {
        const int rowa = wm * 32 + m * 16 + (l >> 2);
        const float rza = 1.0f / sZ[rowa];
        const float rzb = 1.0f / sZ[rowa + 8];
        __half* dsta = g_Upk + (size_t)(q0 + rowa) * (BB * NHD * EE) + bcol * (NHD * EE) + n * EE;
        __half* dstb = dsta + (size_t)8 * (BB * NHD * EE);
        #pragma unroll
        for (int nn = 0; nn < 8; nn++) {
            const int e = nn * 8 + (l & 3) * 2;
            __half2 va = __floats2half2_rn(acc[m][nn][0] * rza, acc[m][nn][1] * rza);
            __half2 vb = __floats2half2_rn(acc[m][nn][2] * rzb, acc[m][nn][3] * rzb);
            *(__half2*)(dsta + e) = va;
            *(__half2*)(dstb + e) = vb;
        }
    }
}

// ---------------------------------------------------------------------------
// Final projection via fp16 mma (unchanged).
__global__ __launch_bounds__(256) void k_proj(const float* __restrict__ bfc,
                                              float* __restrict__ out) {
    __shared__ __half As[128][72];
    __shared__ __half Whs[64][72];
    __shared__ __half Wls[64][72];
    const int t = threadIdx.x;
    const int w = t >> 5, l = t & 31;
    const int q0 = blockIdx.x * 128;
    const int b  = blockIdx.y;
    const int wm = w >> 1, wn = w & 1;

    float acc[2][4][4];
    #pragma unroll
    for (int m = 0; m < 2; m++)
        #pragma unroll
        for (int nt = 0; nt < 4; nt++)
            #pragma unroll
            for (int c = 0; c < 4; c++) acc[m][nt][c] = 0.f;

    for (int fck = 0; fck < 8; fck++) {
        __syncthreads();
        #pragma unroll
        for (int i = 0; i < 4; i++) {
            int idx = t * 4 + i;
            int row = idx >> 3, u = idx & 7;
            uint4 v = *(const uint4*)(g_Upk + (size_t)(q0 + row) * 4096 + b * 512 + fck * 64 + u * 8);
            *(uint4*)(&As[row][u * 8]) = v;
        }
        #pragma unroll
        for (int i = 0; i < 2; i++) {
            int idx = t * 2 + i;
            int eo = idx >> 3, u = idx & 7;
            uint4 vh = *(const uint4*)(g_Wth + eo * 512 + fck * 64 + u * 8);
            uint4 vl = *(const uint4*)(g_Wtl + eo * 512 + fck * 64 + u * 8);
            *(uint4*)(&Whs[eo][u * 8]) = vh;
            *(uint4*)(&Wls[eo][u * 8]) = vl;
        }
        __syncthreads();

        #pragma unroll
        for (int ks = 0; ks < 4; ks++) {
            const int kb = ks * 16;
            uint4 a[2];
            #pragma unroll
            for (int m = 0; m < 2; m++) {
                const int row = wm * 32 + m * 16 + (l >> 2);
                a[m].x = *(const uint32_t*)(&As[row][kb + (l & 3) * 2]);
                a[m].y = *(const uint32_t*)(&As[row + 8][kb + (l & 3) * 2]);
                a[m].z = *(const uint32_t*)(&As[row][kb + 8 + (l & 3) * 2]);
                a[m].w = *(const uint32_t*)(&As[row + 8][kb + 8 + (l & 3) * 2]);
            }
            #pragma unroll
            for (int nt = 0; nt < 4; nt++) {
                const int eo = wn * 32 + nt * 8 + (l >> 2);
                uint2 bh, bl;
                bh.x = *(const uint32_t*)(&Whs[eo][kb + (l & 3) * 2]);
                bh.y = *(const uint32_t*)(&Whs[eo][kb + 8 + (l & 3) * 2]);
                bl.x = *(const uint32_t*)(&Wls[eo][kb + (l & 3) * 2]);
                bl.y = *(const uint32_t*)(&Wls[eo][kb + 8 + (l & 3) * 2]);
                #pragma unroll
                for (int m = 0; m < 2; m++) {
                    mma16816h(acc[m][nt], a[m], bh);
                    mma16816h(acc[m][nt], a[m], bl);
                }
            }
        }
    }

    #pragma unroll
    for (int m = 0; m < 2; m++) {
        const int row = wm * 32 + m * 16 + (l >> 2);
        #pragma unroll
        for (int nt = 0; nt < 4; nt++) {
            const int eo = wn * 32 + nt * 8 + (l & 3) * 2;
            float2 v0 = make_float2(acc[m][nt][0] + bfc[eo], acc[m][nt][1] + bfc[eo + 1]);
            float2 v1 = make_float2(acc[m][nt][2] + bfc[eo], acc[m][nt][3] + bfc[eo + 1]);
            *(float2*)(out + (size_t)(b * NQ + q0 + row) * EE + eo) = v0;
            *(float2*)(out + (size_t)(b * NQ + q0 + row + 8) * EE + eo) = v1;
        }
    }
}

// ---------------------------------------------------------------------------
extern "C" void kernel_launch(void* const* d_in, const int* in_sizes, int n_in,
                              void* d_out, int out_size) {
    const float* hs   = (const float*)d_in[0];
    const float* wsig = (const float*)d_in[3];
    const float* wfc  = (const float*)d_in[5];
    const float* bfc  = (const float*)d_in[6];
    float* out = (float*)d_out;

    cudaFuncSetAttribute(k_attn, cudaFuncAttributeMaxDynamicSharedMemorySize, SMEM_TOTAL);

    k_prep<<<8 + WWB + XPB, 256>>>(hs, wfc, wsig);   // 520 blocks, one launch

    dim3 ga(NQ / QT, NHD, 2);   // (36, 8, 2)
    k_attn<<<ga, 256, SMEM_TOTAL>>>();

    dim3 gp(NQ / 128, BB);      // (18, 8)
    k_proj<<<gp, 256>>>(bfc, out);
}

// round 15
// speedup vs baseline: 1.3940x; 1.1754x over previous
#include <cuda_runtime.h>
#include <cuda_fp16.h>
#include <cstdint>

#define WW 48
#define HH 48
#define NQ 2304
#define NHD 8
#define EE 64
#define BB 8
#define CC 512
#define TW 95
#define LOG2E 1.4426950408889634f

#define QT 64             // M per block (occupancy 2)
#define NCOL 256          // N per block
#define NW32 (CC*NQ/2)    // b32 words in X operand (589824)
#define NWW (EE*CC)       // wsplit items (32768)
#define WWB ((NWW+255)/256) // 128 w-split blocks
#define XPB (BB*48)       // 384 x-pack blocks (b, kx)
#define SKIP_THRESH (-18.0f)

// ---- device scratch ----
__device__ __align__(256) uint4 g_Xbh4[NW32 / 4];   // X fp16, fragment-major [g][kx][ks][lane][word]
__device__ __align__(16) __half g_Upk[NQ * BB * NHD * EE];  // U fp16: [q][b][n*64+e]
__device__ __align__(16) __half g_Wth[EE * CC];     // W^T hi fp16: [eo][f=n*64+e]
__device__ __align__(16) __half g_Wtl[EE * CC];     // W^T lo

__device__ __forceinline__ float fexp2(float x) {
    float y; asm("ex2.approx.ftz.f32 %0, %1;" : "=f"(y) : "f"(x)); return y;
}
__device__ __forceinline__ uint32_t smem_u32(const void* p) {
    uint32_t a;
    asm("{ .reg .u64 t; cvta.to.shared.u64 t, %1; cvt.u32.u64 %0, t; }" : "=r"(a) : "l"(p));
    return a;
}
__device__ __forceinline__ void cpa16(uint32_t dst, const void* src) {
    asm volatile("cp.async.cg.shared.global [%0], [%1], 16;" :: "r"(dst), "l"(src));
}
__device__ __forceinline__ void mma16816h(float* c, const uint4& a, const uint2& b) {
    asm volatile(
        "mma.sync.aligned.m16n8k16.row.col.f32.f16.f16.f32 "
        "{%0,%1,%2,%3}, {%4,%5,%6,%7}, {%8,%9}, {%0,%1,%2,%3};"
        : "+f"(c[0]), "+f"(c[1]), "+f"(c[2]), "+f"(c[3])
        : "r"(a.x), "r"(a.y), "r"(a.z), "r"(a.w), "r"(b.x), "r"(b.y));
}

// Continuous max of f = u0 x + u1 y + u2 x^2 + u3 y^2 + u4 x y over [xlo,xhi]x[ylo,yhi].
// >= max over any grid points inside the rectangle.
__device__ __forceinline__ float qmax_rect(float u0, float u1, float u2, float u3, float u4,
                                           float xlo, float xhi, float ylo, float yhi) {
    auto f = [&](float x, float y) { return u0*x + u1*y + u2*x*x + u3*y*y + u4*x*y; };
    float m = fmaxf(fmaxf(f(xlo, ylo), f(xlo, yhi)), fmaxf(f(xhi, ylo), f(xhi, yhi)));
    if (u3 < 0.f) {
        float yv0 = fminf(fmaxf(-(u1 + u4*xlo) * 0.5f / u3, ylo), yhi);
        float yv1 = fminf(fmaxf(-(u1 + u4*xhi) * 0.5f / u3, ylo), yhi);
        m = fmaxf(m, fmaxf(f(xlo, yv0), f(xhi, yv1)));
    }
    if (u2 < 0.f) {
        float xv0 = fminf(fmaxf(-(u0 + u4*ylo) * 0.5f / u2, xlo), xhi);
        float xv1 = fminf(fmaxf(-(u0 + u4*yhi) * 0.5f / u2, xlo), xhi);
        m = fmaxf(m, fmaxf(f(xv0, ylo), f(xv1, yhi)));
    }
    float det = 4.f*u2*u3 - u4*u4;
    if (u2 < 0.f && det > 0.f) {
        float xs = (u4*u1 - 2.f*u3*u0) / det;
        float ys = (u4*u0 - 2.f*u2*u1) / det;
        if (xs >= xlo && xs <= xhi && ys >= ylo && ys <= yhi) m = fmaxf(m, f(xs, ys));
    }
    return m;
}

// ---------------------------------------------------------------------------
// Prep: W split + X fragment-pack only (max tables are now analytic in k_attn).
__global__ void k_prep(const float* __restrict__ hs, const float* __restrict__ wfc) {
    __shared__ float xs[48 * 64];
    const int bid = blockIdx.x;
    const int t = threadIdx.x;
    if (bid < WWB) {
        int o = bid * 256 + t;
        if (o >= NWW) return;
        int eo = o >> 9, f = o & 511;
        int n = f >> 6, e = f & 63;
        float v = wfc[eo * CC + e * NHD + n];
        __half h = __float2half(v);
        g_Wth[o] = h;
        g_Wtl[o] = __float2half(v - __half2float(h));
    } else {
        const int id2 = bid - WWB;
        const int b  = id2 / 48;
        const int kx = id2 - b * 48;
        const float* src = hs + ((size_t)b * NQ + kx * 48) * EE;
        #pragma unroll
        for (int i = 0; i < 12; i++)
            xs[t + i * 256] = src[t + i * 256];
        __syncthreads();
        #pragma unroll
        for (int i = 0; i < 6; i++) {
            int o2 = t + i * 256;
            int word = o2 & 1;
            int lane = (o2 >> 1) & 31;
            int ks   = (o2 >> 6) % 3;
            int gl   = (o2 >> 6) / 3;
            int n8   = lane >> 2;
            int e    = gl * 8 + n8;
            int kl   = ks * 16 + word * 8 + (lane & 3) * 2;
            float x0 = xs[kl * 64 + e];
            float x1 = xs[(kl + 1) * 64 + e];
            __half2 h = __floats2half2_rn(x0, x1);
            int g = b * 8 + gl;
            int o = ((g * 48 + kx) * 3 + ks) * 64 + lane * 2 + word;
            ((uint32_t*)g_Xbh4)[o] = *(uint32_t*)&h;
        }
    }
}

// ---------------------------------------------------------------------------
// Dynamic smem layout (bytes)
#define SM_STAB 0                 // 49*95*4 = 18620
#define SM_Z    18624             // 64*4 = 256
#define SM_KEEP 18880             // keep[48] | list[48] @+64 | cnt @+128
#define SM_BUF  19072
#define BUFSZ   30720             // Ah 6K | Bh 24K
#define OFF_BH  6144
#define SMEM_TOTAL (SM_BUF + 2 * BUFSZ)   // 80512 -> 2 blocks/SM

// mma.sync fp16 attention GEMM: analytic max, row-skip, 1 barrier/chunk, occ 2.
// Block = (q-tile 64, head, col-half 256), 256 threads.
__global__ __launch_bounds__(256, 2) void k_attn(const float* __restrict__ wsig) {
    extern __shared__ char smem[];
    const uint32_t sb = smem_u32(smem);
    const int t = threadIdx.x;
    const int w = t >> 5, l = t & 31;
    const int q0 = blockIdx.x * QT;
    const int n  = blockIdx.y;
    const int chalf = blockIdx.z;
    const int i0 = q0 / HH;
    const int d0 = 46 - i0;                 // 49-row slice offset

    // head coefficients (raw and log2-scaled)
    const float w0 = __ldg(&wsig[n*5+0]), w1 = __ldg(&wsig[n*5+1]),
                w2 = __ldg(&wsig[n*5+2]), w3 = __ldg(&wsig[n*5+3]),
                w4 = __ldg(&wsig[n*5+4]);
    const float u0 = w0*LOG2E, u1 = w1*LOG2E, u2 = w2*LOG2E,
                u3 = w3*LOG2E, u4 = w4*LOG2E;

    // compute 49-row score-table slice in-kernel (same expression as before)
    float* Stab = (float*)(smem + SM_STAB);
    for (int idx = t; idx < 49 * TW; idx += 256) {
        int r = idx / TW, c = idx - r * TW;
        float dx = (float)(r + d0 - 47);
        float dy = (float)(c - 47);
        Stab[idx] = (w0*dx + w1*dy + w2*dx*dx + w3*dy*dy + w4*dx*dy) * LOG2E;
    }

    // ---- analytic row-skip mask ----
    unsigned char* keep = (unsigned char*)(smem + SM_KEEP);
    unsigned char* list = keep + 64;
    int* pcnt = (int*)(keep + 128);
    if (t < 48) keep[t] = 0;
    __syncthreads();
    {
        const int qq = t & 63, hf = t >> 6;     // hf in [0,4)
        const int qg2 = q0 + qq;
        const int qi2 = qg2 / HH, qj2 = qg2 - qi2 * HH;
        const float xlo = -(float)qi2, xhi = 47.f - qi2;
        const float ylo = -(float)qj2, yhi = 47.f - qj2;
        const float Mq = qmax_rect(u0, u1, u2, u3, u4, xlo, xhi, ylo, yhi);
        #pragma unroll 4
        for (int kx = hf * 12; kx < hf * 12 + 12; kx++) {
            float dxf = (float)(kx - qi2);
            float c1 = u1 + u4 * dxf;
            float base = u0 * dxf + u2 * dxf * dxf;
            float m = fmaxf(c1*ylo + u3*ylo*ylo, c1*yhi + u3*yhi*yhi);
            if (u3 < 0.f) {
                float yv = fminf(fmaxf(-c1 * 0.5f / u3, ylo), yhi);
                m = fmaxf(m, c1*yv + u3*yv*yv);
            }
            if (base + m - Mq > SKIP_THRESH) keep[kx] = 1;
        }
    }
    __syncthreads();
    if (t == 0) {
        int c2 = 0;
        #pragma unroll 8
        for (int kx = 0; kx < 48; kx++) if (keep[kx]) list[c2++] = kx;
        *pcnt = c2;
    }
    __syncthreads();
    const int cnt = *pcnt;

    // producer constants: warp w owns A m-tile mt=w&3; lane rows r0, r0+8
    const int mt = w & 3;
    const int r0 = mt * 16 + (l >> 2);
    const int r1 = r0 + 8;
    const int qa = q0 + r0, qb = q0 + r1;
    const int qi0 = qa / HH, qj0 = qa - qi0 * HH;
    const int qi1 = qb / HH, qj1 = qb - qi1 * HH;
    const float* Sq0 = Stab + (47 - qi0 - d0) * TW + (47 - qj0);
    const float* Sq1 = Stab + (47 - qi1 - d0) * TW + (47 - qj1);
    const float M20 = qmax_rect(u0, u1, u2, u3, u4,
                                -(float)qi0, 47.f - qi0, -(float)qj0, 47.f - qj0);
    const float M21 = qmax_rect(u0, u1, u2, u3, u4,
                                -(float)qi1, 47.f - qi1, -(float)qj1, 47.f - qj1);
    float z0 = 0.f, z1 = 0.f;
    const int kbase = (l & 3) * 2;

    const int seg = t >> 3, uu = t & 7;
    const char* srcH = (const char*)g_Xbh4 + ((size_t)(chalf * 32 + seg) * 48) * 768;

    float acc[2][8][4];
    #pragma unroll
    for (int m = 0; m < 2; m++)
        #pragma unroll
        for (int nn = 0; nn < 8; nn++)
            #pragma unroll
            for (int cdx = 0; cdx < 4; cdx++) acc[m][nn][cdx] = 0.f;

    const int wm = w >> 2, wn = w & 3;

    auto prodKS = [&](int kx, int buf, int ks) {
        char* Ah = smem + SM_BUF + buf * BUFSZ;
        const int kxTW = kx * TW;
        const int ky = ks * 16 + kbase;
        float pa0 = fexp2(Sq0[kxTW + ky]     - M20);
        float pa1 = fexp2(Sq0[kxTW + ky + 1] - M20);
        float pa8 = fexp2(Sq0[kxTW + ky + 8] - M20);
        float pa9 = fexp2(Sq0[kxTW + ky + 9] - M20);
        float pb0 = fexp2(Sq1[kxTW + ky]     - M21);
        float pb1 = fexp2(Sq1[kxTW + ky + 1] - M21);
        float pb8 = fexp2(Sq1[kxTW + ky + 8] - M21);
        float pb9 = fexp2(Sq1[kxTW + ky + 9] - M21);
        z0 += pa0 + pa1 + pa8 + pa9;
        z1 += pb0 + pb1 + pb8 + pb9;
        __half2 h0 = __floats2half2_rn(pa0, pa1);
        __half2 h1 = __floats2half2_rn(pb0, pb1);
        __half2 h2 = __floats2half2_rn(pa8, pa9);
        __half2 h3 = __floats2half2_rn(pb8, pb9);
        const uint32_t off = (uint32_t)(((mt * 3 + ks) * 32 + l) * 16);
        *(uint4*)(Ah + off) = make_uint4(*(uint32_t*)&h0, *(uint32_t*)&h1,
                                         *(uint32_t*)&h2, *(uint32_t*)&h3);
    };
    auto produceA = [&](int kx, int buf) {
        if (w < 4) { prodKS(kx, buf, 0); prodKS(kx, buf, 2); }
        else       { prodKS(kx, buf, 1); }
    };
    auto issueB = [&](int kx, int buf) {
        const uint32_t dBh = sb + SM_BUF + buf * BUFSZ + OFF_BH + seg * 768;
        const char* sH = srcH + (size_t)kx * 768;
        #pragma unroll
        for (int i = 0; i < 6; i++) {
            int u16 = (uu + i * 8) * 16;
            cpa16(dBh + u16, sH + u16);
        }
        asm volatile("cp.async.commit_group;" ::: "memory");
    };
    auto mmaKS = [&](int ks, int buf) {
        const uint4* AhP = (const uint4*)(smem + SM_BUF + buf * BUFSZ);
        const uint2* BhP = (const uint2*)(smem + SM_BUF + buf * BUFSZ + OFF_BH);
        uint4 ah[2];
        #pragma unroll
        for (int m = 0; m < 2; m++)
            ah[m] = AhP[((wm * 2 + m) * 3 + ks) * 32 + l];
        uint2 bh[8];
        #pragma unroll
        for (int nn = 0; nn < 8; nn++)
            bh[nn] = BhP[((wn * 8 + nn) * 3 + ks) * 32 + l];
        #pragma unroll
        for (int m = 0; m < 2; m++)
            #pragma unroll
            for (int nn = 0; nn < 8; nn++)
                mma16816h(acc[m][nn], ah[m], bh[nn]);
    };

    // prologue: fill buffer 0 for the first kept chunk
    produceA(list[0], 0);
    issueB(list[0], 0);

    // ONE barrier per chunk. Writes to buf^1 (A via produceA, B via issueB)
    // happen strictly after the leading sync, whose predecessors include all
    // reads of buf^1 from the previous iteration.
    for (int ic = 0; ic < cnt; ic++) {
        const int buf = ic & 1;
        const bool more = (ic + 1 < cnt);
        asm volatile("cp.async.wait_group 0;" ::: "memory");   // B(ic) arrived
        __syncthreads();
        if (more) issueB(list[ic + 1], buf ^ 1);
        mmaKS(0, buf);
        if (more) produceA(list[ic + 1], buf ^ 1);
        mmaKS(1, buf);
        mmaKS(2, buf);
    }

    // Z: reduce over the 4 lanes sharing l>>2, then merge warp w and w+4
    z0 += __shfl_xor_sync(0xFFFFFFFFu, z0, 1);
    z0 += __shfl_xor_sync(0xFFFFFFFFu, z0, 2);
    z1 += __shfl_xor_sync(0xFFFFFFFFu, z1, 1);
    z1 += __shfl_xor_sync(0xFFFFFFFFu, z1, 2);
    float* sZ = (float*)(smem + SM_Z);
    __syncthreads();                       // all MMA reads done before reuse below
    if (w < 4 && (l & 3) == 0) { sZ[r0] = z0; sZ[r1] = z1; }
    __syncthreads();
    if (w >= 4 && (l & 3) == 0) { sZ[r0] += z0; sZ[r1] += z1; }
    __syncthreads();

    // epilogue: scale by 1/Z, store fp16 to g_Upk[q][b][n*64+e]
    const int bcol = chalf * 4 + wn;
    #pragma unroll
    for (int m = 0; m < 2; m++) {
        const int rowa = wm * 32 + m * 16 + (l >> 2);
        const float rza = 1.0f / sZ[rowa];
        const float rzb = 1.0f / sZ[rowa + 8];
        __half* dsta = g_Upk + (size_t)(q0 + rowa) * (BB * NHD * EE) + bcol * (NHD * EE) + n * EE;
        __half* dstb = dsta + (size_t)8 * (BB * NHD * EE);
        #pragma unroll
        for (int nn = 0; nn < 8; nn++) {
            const int e = nn * 8 + (l & 3) * 2;
            __half2 va = __floats2half2_rn(acc[m][nn][0] * rza, acc[m][nn][1] * rza);
            __half2 vb = __floats2half2_rn(acc[m][nn][2] * rzb, acc[m][nn][3] * rzb);
            *(__half2*)(dsta + e) = va;
            *(__half2*)(dstb + e) = vb;
        }
    }
}

// ---------------------------------------------------------------------------
// Final projection via fp16 mma (unchanged).
__global__ __launch_bounds__(256) void k_proj(const float* __restrict__ bfc,
                                              float* __restrict__ out) {
    __shared__ __half As[128][72];
    __shared__ __half Whs[64][72];
    __shared__ __half Wls[64][72];
    const int t = threadIdx.x;
    const int w = t >> 5, l = t & 31;
    const int q0 = blockIdx.x * 128;
    const int b  = blockIdx.y;
    const int wm = w >> 1, wn = w & 1;

    float acc[2][4][4];
    #pragma unroll
    for (int m = 0; m < 2; m++)
        #pragma unroll
        for (int nt = 0; nt < 4; nt++)
            #pragma unroll
            for (int c = 0; c < 4; c++) acc[m][nt][c] = 0.f;

    for (int fck = 0; fck < 8; fck++) {
        __syncthreads();
        #pragma unroll
        for (int i = 0; i < 4; i++) {
            int idx = t * 4 + i;
            int row = idx >> 3, u = idx & 7;
            uint4 v = *(const uint4*)(g_Upk + (size_t)(q0 + row) * 4096 + b * 512 + fck * 64 + u * 8);
            *(uint4*)(&As[row][u * 8]) = v;
        }
        #pragma unroll
        for (int i = 0; i < 2; i++) {
            int idx = t * 2 + i;
            int eo = idx >> 3, u = idx & 7;
            uint4 vh = *(const uint4*)(g_Wth + eo * 512 + fck * 64 + u * 8);
            uint4 vl = *(const uint4*)(g_Wtl + eo * 512 + fck * 64 + u * 8);
            *(uint4*)(&Whs[eo][u * 8]) = vh;
            *(uint4*)(&Wls[eo][u * 8]) = vl;
        }
        __syncthreads();

        #pragma unroll
        for (int ks = 0; ks < 4; ks++) {
            const int kb = ks * 16;
            uint4 a[2];
            #pragma unroll
            for (int m = 0; m < 2; m++) {
                const int row = wm * 32 + m * 16 + (l >> 2);
                a[m].x = *(const uint32_t*)(&As[row][kb + (l & 3) * 2]);
                a[m].y = *(const uint32_t*)(&As[row + 8][kb + (l & 3) * 2]);
                a[m].z = *(const uint32_t*)(&As[row][kb + 8 + (l & 3) * 2]);
                a[m].w = *(const uint32_t*)(&As[row + 8][kb + 8 + (l & 3) * 2]);
            }
            #pragma unroll
            for (int nt = 0; nt < 4; nt++) {
                const int eo = wn * 32 + nt * 8 + (l >> 2);
                uint2 bh, bl;
                bh.x = *(const uint32_t*)(&Whs[eo][kb + (l & 3) * 2]);
                bh.y = *(const uint32_t*)(&Whs[eo][kb + 8 + (l & 3) * 2]);
                bl.x = *(const uint32_t*)(&Wls[eo][kb + (l & 3) * 2]);
                bl.y = *(const uint32_t*)(&Wls[eo][kb + 8 + (l & 3) * 2]);
                #pragma unroll
                for (int m = 0; m < 2; m++) {
                    mma16816h(acc[m][nt], a[m], bh);
                    mma16816h(acc[m][nt], a[m], bl);
                }
            }
        }
    }

    #pragma unroll
    for (int m = 0; m < 2; m++) {
        const int row = wm * 32 + m * 16 + (l >> 2);
        #pragma unroll
        for (int nt = 0; nt < 4; nt++) {
            const int eo = wn * 32 + nt * 8 + (l & 3) * 2;
            float2 v0 = make_float2(acc[m][nt][0] + bfc[eo], acc[m][nt][1] + bfc[eo + 1]);
            float2 v1 = make_float2(acc[m][nt][2] + bfc[eo], acc[m][nt][3] + bfc[eo + 1]);
            *(float2*)(out + (size_t)(b * NQ + q0 + row) * EE + eo) = v0;
            *(float2*)(out + (size_t)(b * NQ + q0 + row + 8) * EE + eo) = v1;
        }
    }
}

// ---------------------------------------------------------------------------
extern "C" void kernel_launch(void* const* d_in, const int* in_sizes, int n_in,
                              void* d_out, int out_size) {
    const float* hs   = (const float*)d_in[0];
    const float* wsig = (const float*)d_in[3];
    const float* wfc  = (const float*)d_in[5];
    const float* bfc  = (const float*)d_in[6];
    float* out = (float*)d_out;

    cudaFuncSetAttribute(k_attn, cudaFuncAttributeMaxDynamicSharedMemorySize, SMEM_TOTAL);

    k_prep<<<WWB + XPB, 256>>>(hs, wfc);   // 512 blocks, one launch

    dim3 ga(NQ / QT, NHD, 2);   // (36, 8, 2)
    k_attn<<<ga, 256, SMEM_TOTAL>>>(wsig);

    dim3 gp(NQ / 128, BB);      // (18, 8)
    k_proj<<<gp, 256>>>(bfc, out);
}

// round 17
// speedup vs baseline: 1.4623x; 1.0490x over previous
#include <cuda_runtime.h>
#include <cuda_fp16.h>
#include <cstdint>

#define WW 48
#define HH 48
#define NQ 2304
#define NHD 8
#define EE 64
#define BB 8
#define CC 512
#define TW 95
#define LOG2E 1.4426950408889634f

#define QT 64             // M per block (occupancy 2)
#define NCOL 256          // N per block
#define NW32 (CC*NQ/2)    // b32 words in X operand (589824)
#define NWW (EE*CC)       // wsplit items (32768)
#define WWB ((NWW+255)/256) // 128 w-split blocks
#define XPB (BB*48)       // 384 x-pack blocks (b, kx)
#define SKIP_THRESH (-12.0f)

// ---- device scratch ----
__device__ __align__(256) uint4 g_Xbh4[NW32 / 4];   // X fp16, fragment-major [g][kx][ks][lane][word]
__device__ __align__(16) __half g_Upk[NQ * BB * NHD * EE];  // U fp16: [q][b][n*64+e]
__device__ __align__(16) __half g_Wth[EE * CC];     // W^T fp16: [eo][f=n*64+e]

__device__ __forceinline__ float fexp2(float x) {
    float y; asm("ex2.approx.ftz.f32 %0, %1;" : "=f"(y) : "f"(x)); return y;
}
__device__ __forceinline__ uint32_t smem_u32(const void* p) {
    uint32_t a;
    asm("{ .reg .u64 t; cvta.to.shared.u64 t, %1; cvt.u32.u64 %0, t; }" : "=r"(a) : "l"(p));
    return a;
}
__device__ __forceinline__ void cpa16(uint32_t dst, const void* src) {
    asm volatile("cp.async.cg.shared.global [%0], [%1], 16;" :: "r"(dst), "l"(src));
}
__device__ __forceinline__ void mma16816h(float* c, const uint4& a, const uint2& b) {
    asm volatile(
        "mma.sync.aligned.m16n8k16.row.col.f32.f16.f16.f32 "
        "{%0,%1,%2,%3}, {%4,%5,%6,%7}, {%8,%9}, {%0,%1,%2,%3};"
        : "+f"(c[0]), "+f"(c[1]), "+f"(c[2]), "+f"(c[3])
        : "r"(a.x), "r"(a.y), "r"(a.z), "r"(a.w), "r"(b.x), "r"(b.y));
}

// Continuous max of f = u0 x + u1 y + u2 x^2 + u3 y^2 + u4 x y over [xlo,xhi]x[ylo,yhi].
__device__ __forceinline__ float qmax_rect(float u0, float u1, float u2, float u3, float u4,
                                           float xlo, float xhi, float ylo, float yhi) {
    auto f = [&](float x, float y) { return u0*x + u1*y + u2*x*x + u3*y*y + u4*x*y; };
    float m = fmaxf(fmaxf(f(xlo, ylo), f(xlo, yhi)), fmaxf(f(xhi, ylo), f(xhi, yhi)));
    if (u3 < 0.f) {
        float yv0 = fminf(fmaxf(-(u1 + u4*xlo) * 0.5f / u3, ylo), yhi);
        float yv1 = fminf(fmaxf(-(u1 + u4*xhi) * 0.5f / u3, ylo), yhi);
        m = fmaxf(m, fmaxf(f(xlo, yv0), f(xhi, yv1)));
    }
    if (u2 < 0.f) {
        float xv0 = fminf(fmaxf(-(u0 + u4*ylo) * 0.5f / u2, xlo), xhi);
        float xv1 = fminf(fmaxf(-(u0 + u4*yhi) * 0.5f / u2, xlo), xhi);
        m = fmaxf(m, fmaxf(f(xv0, ylo), f(xv1, yhi)));
    }
    float det = 4.f*u2*u3 - u4*u4;
    if (u2 < 0.f && det > 0.f) {
        float xs = (u4*u1 - 2.f*u3*u0) / det;
        float ys = (u4*u0 - 2.f*u2*u1) / det;
        if (xs >= xlo && xs <= xhi && ys >= ylo && ys <= yhi) m = fmaxf(m, f(xs, ys));
    }
    return m;
}

// ---------------------------------------------------------------------------
// Prep: W pack (single fp16) + X fragment-pack.
__global__ void k_prep(const float* __restrict__ hs, const float* __restrict__ wfc) {
    __shared__ float xs[48 * 64];
    const int bid = blockIdx.x;
    const int t = threadIdx.x;
    if (bid < WWB) {
        int o = bid * 256 + t;
        if (o >= NWW) return;
        int eo = o >> 9, f = o & 511;
        int n = f >> 6, e = f & 63;
        g_Wth[o] = __float2half(wfc[eo * CC + e * NHD + n]);
    } else {
        const int id2 = bid - WWB;
        const int b  = id2 / 48;
        const int kx = id2 - b * 48;
        const float* src = hs + ((size_t)b * NQ + kx * 48) * EE;
        #pragma unroll
        for (int i = 0; i < 12; i++)
            xs[t + i * 256] = src[t + i * 256];
        __syncthreads();
        #pragma unroll
        for (int i = 0; i < 6; i++) {
            int o2 = t + i * 256;
            int word = o2 & 1;
            int lane = (o2 >> 1) & 31;
            int ks   = (o2 >> 6) % 3;
            int gl   = (o2 >> 6) / 3;
            int n8   = lane >> 2;
            int e    = gl * 8 + n8;
            int kl   = ks * 16 + word * 8 + (lane & 3) * 2;
            float x0 = xs[kl * 64 + e];
            float x1 = xs[(kl + 1) * 64 + e];
            __half2 h = __floats2half2_rn(x0, x1);
            int g = b * 8 + gl;
            int o = ((g * 48 + kx) * 3 + ks) * 64 + lane * 2 + word;
            ((uint32_t*)g_Xbh4)[o] = *(uint32_t*)&h;
        }
    }
}

// ---------------------------------------------------------------------------
// Dynamic smem layout (bytes)
#define SM_STAB 0                 // 49*95*4 = 18620
#define SM_Z    18624             // 64*4 = 256
#define SM_KEEP 18880             // keep[48] | list[48] @+64 | cnt @+128
#define SM_BUF  19072
#define BUFSZ   30720             // Ah 6K | Bh 24K
#define OFF_BH  6144
#define SMEM_TOTAL (SM_BUF + 2 * BUFSZ)   // 80512 -> 2 blocks/SM

// mma.sync fp16 attention GEMM: analytic max, row-skip, 1 barrier/chunk, occ 2.
__global__ __launch_bounds__(256, 2) void k_attn(const float* __restrict__ wsig) {
    extern __shared__ char smem[];
    const uint32_t sb = smem_u32(smem);
    const int t = threadIdx.x;
    const int w = t >> 5, l = t & 31;
    const int q0 = blockIdx.x * QT;
    const int n  = blockIdx.y;
    const int chalf = blockIdx.z;
    const int i0 = q0 / HH;
    const int d0 = 46 - i0;                 // 49-row slice offset

    const float w0 = __ldg(&wsig[n*5+0]), w1 = __ldg(&wsig[n*5+1]),
                w2 = __ldg(&wsig[n*5+2]), w3 = __ldg(&wsig[n*5+3]),
                w4 = __ldg(&wsig[n*5+4]);
    const float u0 = w0*LOG2E, u1 = w1*LOG2E, u2 = w2*LOG2E,
                u3 = w3*LOG2E, u4 = w4*LOG2E;

    float* Stab = (float*)(smem + SM_STAB);
    for (int idx = t; idx < 49 * TW; idx += 256) {
        int r = idx / TW, c = idx - r * TW;
        float dx = (float)(r + d0 - 47);
        float dy = (float)(c - 47);
        Stab[idx] = (w0*dx + w1*dy + w2*dx*dx + w3*dy*dy + w4*dx*dy) * LOG2E;
    }

    // ---- analytic row-skip mask ----
    unsigned char* keep = (unsigned char*)(smem + SM_KEEP);
    unsigned char* list = keep + 64;
    int* pcnt = (int*)(keep + 128);
    if (t < 48) keep[t] = 0;
    __syncthreads();
    {
        const int qq = t & 63, hf = t >> 6;
        const int qg2 = q0 + qq;
        const int qi2 = qg2 / HH, qj2 = qg2 - qi2 * HH;
        const float xlo = -(float)qi2, xhi = 47.f - qi2;
        const float ylo = -(float)qj2, yhi = 47.f - qj2;
        const float Mq = qmax_rect(u0, u1, u2, u3, u4, xlo, xhi, ylo, yhi);
        #pragma unroll 4
        for (int kx = hf * 12; kx < hf * 12 + 12; kx++) {
            float dxf = (float)(kx - qi2);
            float c1 = u1 + u4 * dxf;
            float base = u0 * dxf + u2 * dxf * dxf;
            float m = fmaxf(c1*ylo + u3*ylo*ylo, c1*yhi + u3*yhi*yhi);
            if (u3 < 0.f) {
                float yv = fminf(fmaxf(-c1 * 0.5f / u3, ylo), yhi);
                m = fmaxf(m, c1*yv + u3*yv*yv);
            }
            if (base + m - Mq > SKIP_THRESH) keep[kx] = 1;
        }
    }
    __syncthreads();
    if (t == 0) {
        int c2 = 0;
        #pragma unroll 8
        for (int kx = 0; kx < 48; kx++) if (keep[kx]) list[c2++] = kx;
        *pcnt = c2;
    }
    __syncthreads();
    const int cnt = *pcnt;

    const int mt = w & 3;
    const int r0 = mt * 16 + (l >> 2);
    const int r1 = r0 + 8;
    const int qa = q0 + r0, qb = q0 + r1;
    const int qi0 = qa / HH, qj0 = qa - qi0 * HH;
    const int qi1 = qb / HH, qj1 = qb - qi1 * HH;
    const float* Sq0 = Stab + (47 - qi0 - d0) * TW + (47 - qj0);
    const float* Sq1 = Stab + (47 - qi1 - d0) * TW + (47 - qj1);
    const float M20 = qmax_rect(u0, u1, u2, u3, u4,
                                -(float)qi0, 47.f - qi0, -(float)qj0, 47.f - qj0);
    const float M21 = qmax_rect(u0, u1, u2, u3, u4,
                                -(float)qi1, 47.f - qi1, -(float)qj1, 47.f - qj1);
    float z0 = 0.f, z1 = 0.f;
    const int kbase = (l & 3) * 2;

    const int seg = t >> 3, uu = t & 7;
    const char* srcH = (const char*)g_Xbh4 + ((size_t)(chalf * 32 + seg) * 48) * 768;

    float acc[2][8][4];
    #pragma unroll
    for (int m = 0; m < 2; m++)
        #pragma unroll
        for (int nn = 0; nn < 8; nn++)
            #pragma unroll
            for (int cdx = 0; cdx < 4; cdx++) acc[m][nn][cdx] = 0.f;

    const int wm = w >> 2, wn = w & 3;

    auto prodKS = [&](int kx, int buf, int ks) {
        char* Ah = smem + SM_BUF + buf * BUFSZ;
        const int kxTW = kx * TW;
        const int ky = ks * 16 + kbase;
        float pa0 = fexp2(Sq0[kxTW + ky]     - M20);
        float pa1 = fexp2(Sq0[kxTW + ky + 1] - M20);
        float pa8 = fexp2(Sq0[kxTW + ky + 8] - M20);
        float pa9 = fexp2(Sq0[kxTW + ky + 9] - M20);
        float pb0 = fexp2(Sq1[kxTW + ky]     - M21);
        float pb1 = fexp2(Sq1[kxTW + ky + 1] - M21);
        float pb8 = fexp2(Sq1[kxTW + ky + 8] - M21);
        float pb9 = fexp2(Sq1[kxTW + ky + 9] - M21);
        z0 += pa0 + pa1 + pa8 + pa9;
        z1 += pb0 + pb1 + pb8 + pb9;
        __half2 h0 = __floats2half2_rn(pa0, pa1);
        __half2 h1 = __floats2half2_rn(pb0, pb1);
        __half2 h2 = __floats2half2_rn(pa8, pa9);
        __half2 h3 = __floats2half2_rn(pb8, pb9);
        const uint32_t off = (uint32_t)(((mt * 3 + ks) * 32 + l) * 16);
        *(uint4*)(Ah + off) = make_uint4(*(uint32_t*)&h0, *(uint32_t*)&h1,
                                         *(uint32_t*)&h2, *(uint32_t*)&h3);
    };
    auto produceA = [&](int kx, int buf) {
        if (w < 4) { prodKS(kx, buf, 0); prodKS(kx, buf, 2); }
        else       { prodKS(kx, buf, 1); }
    };
    auto issueB = [&](int kx, int buf) {
        const uint32_t dBh = sb + SM_BUF + buf * BUFSZ + OFF_BH + seg * 768;
        const char* sH = srcH + (size_t)kx * 768;
        #pragma unroll
        for (int i = 0; i < 6; i++) {
            int u16 = (uu + i * 8) * 16;
            cpa16(dBh + u16, sH + u16);
        }
        asm volatile("cp.async.commit_group;" ::: "memory");
    };
    auto mmaKS = [&](int ks, int buf) {
        const uint4* AhP = (const uint4*)(smem + SM_BUF + buf * BUFSZ);
        const uint2* BhP = (const uint2*)(smem + SM_BUF + buf * BUFSZ + OFF_BH);
        uint4 ah[2];
        #pragma unroll
        for (int m = 0; m < 2; m++)
            ah[m] = AhP[((wm * 2 + m) * 3 + ks) * 32 + l];
        uint2 bh[8];
        #pragma unroll
        for (int nn = 0; nn < 8; nn++)
            bh[nn] = BhP[((wn * 8 + nn) * 3 + ks) * 32 + l];
        #pragma unroll
        for (int m = 0; m < 2; m++)
            #pragma unroll
            for (int nn = 0; nn < 8; nn++)
                mma16816h(acc[m][nn], ah[m], bh[nn]);
    };

    produceA(list[0], 0);
    issueB(list[0], 0);

    for (int ic = 0; ic < cnt; ic++) {
        const int buf = ic & 1;
        const bool more = (ic + 1 < cnt);
        asm volatile("cp.async.wait_group 0;" ::: "memory");
        __syncthreads();
        if (more) issueB(list[ic + 1], buf ^ 1);
        mmaKS(0, buf);
        if (more) produceA(list[ic + 1], buf ^ 1);
        mmaKS(1, buf);
        mmaKS(2, buf);
    }

    z0 += __shfl_xor_sync(0xFFFFFFFFu, z0, 1);
    z0 += __shfl_xor_sync(0xFFFFFFFFu, z0, 2);
    z1 += __shfl_xor_sync(0xFFFFFFFFu, z1, 1);
    z1 += __shfl_xor_sync(0xFFFFFFFFu, z1, 2);
    float* sZ = (float*)(smem + SM_Z);
    __syncthreads();
    if (w < 4 && (l & 3) == 0) { sZ[r0] = z0; sZ[r1] = z1; }
    __syncthreads();
    if (w >= 4 && (l & 3) == 0) { sZ[r0] += z0; sZ[r1] += z1; }
    __syncthreads();

    const int bcol = chalf * 4 + wn;
    #pragma unroll
    for (int m = 0; m < 2; m++) {
        const int rowa = wm * 32 + m * 16 + (l >> 2);
        const float rza = 1.0f / sZ[rowa];
        const float rzb = 1.0f / sZ[rowa + 8];
        __half* dsta = g_Upk + (size_t)(q0 + rowa) * (BB * NHD * EE) + bcol * (NHD * EE) + n * EE;
        __half* dstb = dsta + (size_t)8 * (BB * NHD * EE);
        #pragma unroll
        for (int nn = 0; nn < 8; nn++) {
            const int e = nn * 8 + (l & 3) * 2;
            __half2 va = __floats2half2_rn(acc[m][nn][0] * rza, acc[m][nn][1] * rza);
            __half2 vb = __floats2half2_rn(acc[m][nn][2] * rzb, acc[m][nn][3] * rzb);
            *(__half2*)(dsta + e) = va;
            *(__half2*)(dstb + e) = vb;
        }
    }
}

// ---------------------------------------------------------------------------
// Final projection via fp16 mma, single-pass W.
__global__ __launch_bounds__(256) void k_proj(const float* __restrict__ bfc,
                                              float* __restrict__ out) {
    __shared__ __half As[128][72];
    __shared__ __half Whs[64][72];
    const int t = threadIdx.x;
    const int w = t >> 5, l = t & 31;
    const int q0 = blockIdx.x * 128;
    const int b  = blockIdx.y;
    const int wm = w >> 1, wn = w & 1;

    float acc[2][4][4];
    #pragma unroll
    for (int m = 0; m < 2; m++)
        #pragma unroll
        for (int nt = 0; nt < 4; nt++)
            #pragma unroll
            for (int c = 0; c < 4; c++) acc[m][nt][c] = 0.f;

    for (int fck = 0; fck < 8; fck++) {
        __syncthreads();
        #pragma unroll
        for (int i = 0; i < 4; i++) {
            int idx = t * 4 + i;
            int row = idx >> 3, u = idx & 7;
            uint4 v = *(const uint4*)(g_Upk + (size_t)(q0 + row) * 4096 + b * 512 + fck * 64 + u * 8);
            *(uint4*)(&As[row][u * 8]) = v;
        }
        {
            int idx = t * 2;
            int eo = idx >> 3, u = idx & 7;
            uint4 vh = *(const uint4*)(g_Wth + eo * 512 + fck * 64 + u * 8);
            *(uint4*)(&Whs[eo][u * 8]) = vh;
            int idx2 = idx + 1;
            int eo2 = idx2 >> 3, u2 = idx2 & 7;
            uint4 vh2 = *(const uint4*)(g_Wth + eo2 * 512 + fck * 64 + u2 * 8);
            *(uint4*)(&Whs[eo2][u2 * 8]) = vh2;
        }
        __syncthreads();

        #pragma unroll
        for (int ks = 0; ks < 4; ks++) {
            const int kb = ks * 16;
            uint4 a[2];
            #pragma unroll
            for (int m = 0; m < 2; m++) {
                const int row = wm * 32 + m * 16 + (l >> 2);
                a[m].x = *(const uint32_t*)(&As[row][kb + (l & 3) * 2]);
                a[m].y = *(const uint32_t*)(&As[row + 8][kb + (l & 3) * 2]);
                a[m].z = *(const uint32_t*)(&As[row][kb + 8 + (l & 3) * 2]);
                a[m].w = *(const uint32_t*)(&As[row + 8][kb + 8 + (l & 3) * 2]);
            }
            #pragma unroll
            for (int nt = 0; nt < 4; nt++) {
                const int eo = wn * 32 + nt * 8 + (l >> 2);
                uint2 bh;
                bh.x = *(const uint32_t*)(&Whs[eo][kb + (l & 3) * 2]);
                bh.y = *(const uint32_t*)(&Whs[eo][kb + 8 + (l & 3) * 2]);
                #pragma unroll
                for (int m = 0; m < 2; m++)
                    mma16816h(acc[m][nt], a[m], bh);
            }
        }
    }

    #pragma unroll
    for (int m = 0; m < 2; m++) {
        const int row = wm * 32 + m * 16 + (l >> 2);
        #pragma unroll
        for (int nt = 0; nt < 4; nt++) {
            const int eo = wn * 32 + nt * 8 + (l & 3) * 2;
            float2 v0 = make_float2(acc[m][nt][0] + bfc[eo], acc[m][nt][1] + bfc[eo + 1]);
            float2 v1 = make_float2(acc[m][nt][2] + bfc[eo], acc[m][nt][3] + bfc[eo + 1]);
            *(float2*)(out + (size_t)(b * NQ + q0 + row) * EE + eo) = v0;
            *(float2*)(out + (size_t)(b * NQ + q0 + row + 8) * EE + eo) = v1;
        }
    }
}

// ---------------------------------------------------------------------------
extern "C" void kernel_launch(void* const* d_in, const int* in_sizes, int n_in,
                              void* d_out, int out_size) {
    const float* hs   = (const float*)d_in[0];
    const float* wsig = (const float*)d_in[3];
    const float* wfc  = (const float*)d_in[5];
    const float* bfc  = (const float*)d_in[6];
    float* out = (float*)d_out;

    cudaFuncSetAttribute(k_attn, cudaFuncAttributeMaxDynamicSharedMemorySize, SMEM_TOTAL);

    k_prep<<<WWB + XPB, 256>>>(hs, wfc);   // 512 blocks, one launch

    dim3 ga(NQ / QT, NHD, 2);   // (36, 8, 2)
    k_attn<<<ga, 256, SMEM_TOTAL>>>(wsig);

    dim3 gp(NQ / 128, BB);      // (18, 8)
    k_proj<<<gp, 256>>>(bfc, out);
}